// round 8
// baseline (speedup 1.0000x reference)
#include <cuda_runtime.h>
#include <cuda_fp16.h>
#include <cstdint>

// Problem dims
#define BB 8
#define SS 2048
#define DMODEL 1024
#define HDIM 64
#define NHEADS 16
#define MTOT (BB * SS)   // 16384 tokens
#define NSPLIT 4         // KV splits
#define KPS (SS / NSPLIT) // 512 keys per split

// ---------------------------------------------------------------------------
// Scratch (fp16 operands, fp32 partials).
// q,k,ctx: [token][64] row-major.  v: TRANSPOSED [b][dim][s].  wo: [n][d].
// ---------------------------------------------------------------------------
__device__ __half g_qh[MTOT * HDIM];
__device__ __half g_kh[MTOT * HDIM];
__device__ __half g_vh[MTOT * HDIM];     // [b][dim][s]
__device__ __half g_ch[MTOT * HDIM];
__device__ __half g_woh[DMODEL * HDIM];  // [n][d]
// Split-KV partials (fp32, unnormalized o; m,l in log2 domain)
__device__ float g_po[NSPLIT * MTOT * HDIM];
__device__ float g_pm[NSPLIT * MTOT];
__device__ float g_pl[NSPLIT * MTOT];

// ---------------------------------------------------------------------------
// Helpers
// ---------------------------------------------------------------------------
__device__ __forceinline__ void mma_fp16(float c[4],
                                         uint32_t a0, uint32_t a1, uint32_t a2, uint32_t a3,
                                         uint32_t b0, uint32_t b1) {
    asm volatile(
        "mma.sync.aligned.m16n8k16.row.col.f32.f16.f16.f32 "
        "{%0,%1,%2,%3}, {%4,%5,%6,%7}, {%8,%9}, {%0,%1,%2,%3};\n"
        : "+f"(c[0]), "+f"(c[1]), "+f"(c[2]), "+f"(c[3])
        : "r"(a0), "r"(a1), "r"(a2), "r"(a3), "r"(b0), "r"(b1));
}

__device__ __forceinline__ uint32_t pack2h(float x, float y) {
    __half2 h = __floats2half2_rn(x, y);
    return *reinterpret_cast<uint32_t*>(&h);
}

// Word permutation: fragment word pair (kc*8+tig, kc*8+4+tig) -> adjacent.
// gw = kc*8 + j, j = tig + 4b  ->  dst = kc*8 + 2*tig + b
__device__ __forceinline__ int permw(int gw) {
    int kc = gw >> 3, j = gw & 7;
    return kc * 8 + ((j & 3) << 1) + (j >> 2);
}

// ---------------------------------------------------------------------------
// Kernel 1: Wo_sum^T[n][d] = sum_h Wo[h*64+d][n]  (fp16)
// ---------------------------------------------------------------------------
__global__ void wosum_kernel(const float* __restrict__ Wo) {
    int idx = blockIdx.x * blockDim.x + threadIdx.x;   // 0..65535
    int d = idx >> 10;
    int n = idx & (DMODEL - 1);
    float s = 0.f;
#pragma unroll
    for (int h = 0; h < NHEADS; h++)
        s += Wo[(h * HDIM + d) * DMODEL + n];
    g_woh[n * HDIM + d] = __float2half_rn(s);
}

// ---------------------------------------------------------------------------
// Kernel 2: fused q/k/v projections (fp16 MMA, fp32 accum).
// BM=128, BN=64, BK=32. 256 thr, 8 warps. Register double-buffered loads.
// Paired-word smem layout (pitch 20 u32) -> LDS.64 fragments.
// ---------------------------------------------------------------------------
#define QSCALE (0.125f * 1.4426950408889634f)
__global__ __launch_bounds__(256) void proj_kernel(
    const float* __restrict__ Xq, const float* __restrict__ Xk, const float* __restrict__ Xv,
    const float* __restrict__ Wq, const float* __restrict__ Wk, const float* __restrict__ Wv,
    const float* __restrict__ bq, const float* __restrict__ bk, const float* __restrict__ bv) {

    const int which = blockIdx.y;
    const float* X;  const float* W;  const float* bias;
    if (which == 0)      { X = Xq; W = Wq; bias = bq; }
    else if (which == 1) { X = Xk; W = Wk; bias = bk; }
    else                 { X = Xv; W = Wv; bias = bv; }

    __shared__ uint32_t As32[128 * 20];
    __shared__ uint32_t Bs32[64 * 20];
    __half* Bs16 = (__half*)Bs32;

    const int tid  = threadIdx.x;
    const int warp = tid >> 5, lane = tid & 31;
    const int g = lane >> 2, tig = lane & 3;
    const int wm = warp & 3, wn = warp >> 2;
    const int row0 = blockIdx.x * 128;

    float c[2][4][4];
#pragma unroll
    for (int mt = 0; mt < 2; mt++)
#pragma unroll
        for (int nt = 0; nt < 4; nt++)
#pragma unroll
            for (int j = 0; j < 4; j++) c[mt][nt][j] = 0.f;

    // Register staging for next tile
    float4 xa[4], wb[2];
    {
#pragma unroll
        for (int it = 0; it < 4; it++) {
            int id = tid + it * 256;
            int r = id >> 3, cg = (id & 7) * 4;
            xa[it] = *(const float4*)(X + (row0 + r) * DMODEL + cg);
        }
#pragma unroll
        for (int it = 0; it < 2; it++) {
            int id = tid + it * 256;
            int kr = id >> 4, cg = (id & 15) * 4;
            wb[it] = *(const float4*)(W + kr * HDIM + cg);
        }
    }

    for (int k0 = 0; k0 < DMODEL; k0 += 32) {
        // Store staged regs -> smem (permuted layout)
#pragma unroll
        for (int it = 0; it < 4; it++) {
            int id = tid + it * 256;
            int r = id >> 3, wp = (id & 7) * 2;
            As32[r * 20 + permw(wp)]     = pack2h(xa[it].x, xa[it].y);
            As32[r * 20 + permw(wp + 1)] = pack2h(xa[it].z, xa[it].w);
        }
#pragma unroll
        for (int it = 0; it < 2; it++) {
            int id = tid + it * 256;
            int kr = id >> 4, cg = (id & 15) * 4;
            int ph = 2 * permw(kr >> 1) + (kr & 1);
            Bs16[(cg + 0) * 40 + ph] = __float2half_rn(wb[it].x);
            Bs16[(cg + 1) * 40 + ph] = __float2half_rn(wb[it].y);
            Bs16[(cg + 2) * 40 + ph] = __float2half_rn(wb[it].z);
            Bs16[(cg + 3) * 40 + ph] = __float2half_rn(wb[it].w);
        }
        __syncthreads();

        // Prefetch next tile (overlaps with MMAs below)
        if (k0 + 32 < DMODEL) {
#pragma unroll
            for (int it = 0; it < 4; it++) {
                int id = tid + it * 256;
                int r = id >> 3, cg = (id & 7) * 4;
                xa[it] = *(const float4*)(X + (row0 + r) * DMODEL + k0 + 32 + cg);
            }
#pragma unroll
            for (int it = 0; it < 2; it++) {
                int id = tid + it * 256;
                int kr = id >> 4, cg = (id & 15) * 4;
                wb[it] = *(const float4*)(W + (k0 + 32 + kr) * HDIM + cg);
            }
        }

#pragma unroll
        for (int kk = 0; kk < 2; kk++) {
            uint2 aa[2], ab[2];
#pragma unroll
            for (int mt = 0; mt < 2; mt++) {
                int r = wm * 32 + mt * 16 + g;
                aa[mt] = *(const uint2*)&As32[r * 20 + kk * 8 + 2 * tig];
                ab[mt] = *(const uint2*)&As32[(r + 8) * 20 + kk * 8 + 2 * tig];
            }
#pragma unroll
            for (int nt = 0; nt < 4; nt++) {
                int n = wn * 32 + nt * 8 + g;
                uint2 bb = *(const uint2*)&Bs32[n * 20 + kk * 8 + 2 * tig];
#pragma unroll
                for (int mt = 0; mt < 2; mt++)
                    mma_fp16(c[mt][nt], aa[mt].x, ab[mt].x, aa[mt].y, ab[mt].y, bb.x, bb.y);
            }
        }
        __syncthreads();
    }

    const float scale = (which == 0) ? QSCALE : 1.0f;
    __half* oh = (which == 0) ? g_qh : g_kh;

#pragma unroll
    for (int mt = 0; mt < 2; mt++) {
#pragma unroll
        for (int nt = 0; nt < 4; nt++) {
            int r   = row0 + wm * 32 + mt * 16 + g;
            int col = wn * 32 + nt * 8 + 2 * tig;
            float bv0 = bias[col], bv1 = bias[col + 1];
            float v0 = (c[mt][nt][0] + bv0) * scale;
            float v1 = (c[mt][nt][1] + bv1) * scale;
            float v2 = (c[mt][nt][2] + bv0) * scale;   // row r+8
            float v3 = (c[mt][nt][3] + bv1) * scale;
            if (which < 2) {
                *(uint32_t*)&oh[r * HDIM + col]       = pack2h(v0, v1);
                *(uint32_t*)&oh[(r + 8) * HDIM + col] = pack2h(v2, v3);
            } else {
                // v transposed: [b][dim][s]
                int b = r >> 11, s = r & 2047;
                g_vh[(b * HDIM + col) * SS + s]         = __float2half_rn(v0);
                g_vh[(b * HDIM + col + 1) * SS + s]     = __float2half_rn(v1);
                g_vh[(b * HDIM + col) * SS + s + 8]     = __float2half_rn(v2);
                g_vh[(b * HDIM + col + 1) * SS + s + 8] = __float2half_rn(v3);
            }
        }
    }
}

// ---------------------------------------------------------------------------
// Kernel 3: split-KV flash attention (fp16 tensor cores).
// grid (S/64, B, NSPLIT); block 128 (4 warps, warp owns 16 q-rows).
// Paired-word smem layout (pitch 36 u32) -> LDS.64 fragments.
// Deferred per-lane l accumulation (reduced once at epilogue).
// ---------------------------------------------------------------------------
__global__ __launch_bounds__(128) void attn_kernel() {
    extern __shared__ uint32_t sm32[];
    uint32_t* Qs = sm32;                 // [64][36]
    uint32_t* Ks = sm32 + 64 * 36;
    uint32_t* Vs = sm32 + 2 * 64 * 36;

    const int tid = threadIdx.x, warp = tid >> 5, lane = tid & 31;
    const int g = lane >> 2, tig = lane & 3;
    const int bq = blockIdx.x, b = blockIdx.y, split = blockIdx.z;
    const int t0 = b * SS + bq * 64;
    const int kt0 = split * (KPS / 64);

    const uint32_t* qb32 = (const uint32_t*)g_qh;
    const uint32_t* kb32 = (const uint32_t*)(g_kh + (size_t)b * SS * HDIM);
    const uint32_t* vb32 = (const uint32_t*)(g_vh + (size_t)b * HDIM * SS);

    // Stage Q (permuted)
#pragma unroll
    for (int it = 0; it < 16; it++) {
        int id = tid + it * 128;
        int r = id >> 5, gw = id & 31;
        Qs[r * 36 + permw(gw)] = qb32[(t0 + r) * 32 + gw];
    }

    float m0 = -1e30f, m1 = -1e30f, l0 = 0.f, l1 = 0.f;   // l: per-lane partial
    float o[8][4];
#pragma unroll
    for (int nt = 0; nt < 8; nt++)
#pragma unroll
        for (int j = 0; j < 4; j++) o[nt][j] = 0.f;

    for (int kt = kt0; kt < kt0 + KPS / 64; kt++) {
#pragma unroll
        for (int it = 0; it < 16; it++) {
            int id = tid + it * 128;
            int r = id >> 5, gw = id & 31;
            int dst = r * 36 + permw(gw);
            Ks[dst] = kb32[(kt * 64 + r) * 32 + gw];
            Vs[dst] = vb32[r * 1024 + kt * 32 + gw];
        }
        __syncthreads();

        // S = Q K^T
        float s[8][4];
#pragma unroll
        for (int nt = 0; nt < 8; nt++)
#pragma unroll
            for (int j = 0; j < 4; j++) s[nt][j] = 0.f;

#pragma unroll
        for (int kc = 0; kc < 4; kc++) {
            const int r = warp * 16 + g;
            uint2 qa = *(const uint2*)&Qs[r * 36 + kc * 8 + 2 * tig];
            uint2 qb = *(const uint2*)&Qs[(r + 8) * 36 + kc * 8 + 2 * tig];
#pragma unroll
            for (int nt = 0; nt < 8; nt++) {
                int n = nt * 8 + g;
                uint2 kf = *(const uint2*)&Ks[n * 36 + kc * 8 + 2 * tig];
                mma_fp16(s[nt], qa.x, qb.x, qa.y, qb.y, kf.x, kf.y);
            }
        }

        // Online softmax, base-2 domain. Max reduced across tig; l deferred.
        float mt0 = -1e30f, mt1 = -1e30f;
#pragma unroll
        for (int nt = 0; nt < 8; nt++) {
            mt0 = fmaxf(mt0, fmaxf(s[nt][0], s[nt][1]));
            mt1 = fmaxf(mt1, fmaxf(s[nt][2], s[nt][3]));
        }
        mt0 = fmaxf(mt0, __shfl_xor_sync(0xffffffffu, mt0, 1));
        mt0 = fmaxf(mt0, __shfl_xor_sync(0xffffffffu, mt0, 2));
        mt1 = fmaxf(mt1, __shfl_xor_sync(0xffffffffu, mt1, 1));
        mt1 = fmaxf(mt1, __shfl_xor_sync(0xffffffffu, mt1, 2));
        float mn0 = fmaxf(m0, mt0), mn1 = fmaxf(m1, mt1);
        float cr0 = exp2f(m0 - mn0), cr1 = exp2f(m1 - mn1);
        m0 = mn0; m1 = mn1;
        float ls0 = 0.f, ls1 = 0.f;
#pragma unroll
        for (int nt = 0; nt < 8; nt++) {
            s[nt][0] = exp2f(s[nt][0] - mn0); ls0 += s[nt][0];
            s[nt][1] = exp2f(s[nt][1] - mn0); ls0 += s[nt][1];
            s[nt][2] = exp2f(s[nt][2] - mn1); ls1 += s[nt][2];
            s[nt][3] = exp2f(s[nt][3] - mn1); ls1 += s[nt][3];
        }
        l0 = l0 * cr0 + ls0;      // per-lane partial (cr uniform across tig)
        l1 = l1 * cr1 + ls1;
#pragma unroll
        for (int nt = 0; nt < 8; nt++) {
            o[nt][0] *= cr0; o[nt][1] *= cr0;
            o[nt][2] *= cr1; o[nt][3] *= cr1;
        }

        // ctx += P V  (P fragments straight from accumulators)
#pragma unroll
        for (int kc = 0; kc < 4; kc++) {
            uint32_t ph0 = pack2h(s[2 * kc][0],     s[2 * kc][1]);
            uint32_t ph1 = pack2h(s[2 * kc][2],     s[2 * kc][3]);
            uint32_t ph2 = pack2h(s[2 * kc + 1][0], s[2 * kc + 1][1]);
            uint32_t ph3 = pack2h(s[2 * kc + 1][2], s[2 * kc + 1][3]);
#pragma unroll
            for (int nt = 0; nt < 8; nt++) {
                int n = nt * 8 + g;
                uint2 vf = *(const uint2*)&Vs[n * 36 + kc * 8 + 2 * tig];
                mma_fp16(o[nt], ph0, ph1, ph2, ph3, vf.x, vf.y);
            }
        }
        __syncthreads();
    }

    // Final l reduction across the 4 tig lanes
    l0 += __shfl_xor_sync(0xffffffffu, l0, 1);
    l0 += __shfl_xor_sync(0xffffffffu, l0, 2);
    l1 += __shfl_xor_sync(0xffffffffu, l1, 1);
    l1 += __shfl_xor_sync(0xffffffffu, l1, 2);

    // Write unnormalized partials
    const int r = t0 + warp * 16 + g;
    float* po = g_po + (size_t)split * MTOT * HDIM;
#pragma unroll
    for (int nt = 0; nt < 8; nt++) {
        int col = nt * 8 + 2 * tig;
        *(float2*)&po[r * HDIM + col]       = make_float2(o[nt][0], o[nt][1]);
        *(float2*)&po[(r + 8) * HDIM + col] = make_float2(o[nt][2], o[nt][3]);
    }
    if (tig == 0) {
        g_pm[split * MTOT + r]     = m0;
        g_pm[split * MTOT + r + 8] = m1;
        g_pl[split * MTOT + r]     = l0;
        g_pl[split * MTOT + r + 8] = l1;
    }
}

// ---------------------------------------------------------------------------
// Kernel 3b: combine split-KV partials -> ctx (fp16).
// ---------------------------------------------------------------------------
__global__ __launch_bounds__(256) void combine_kernel() {
    const int warp = threadIdx.x >> 5, lane = threadIdx.x & 31;
    const int row = blockIdx.x * 8 + warp;
    const int col = lane * 2;

    float m[NSPLIT], lpart[NSPLIT];
    float M = -1e30f;
#pragma unroll
    for (int i = 0; i < NSPLIT; i++) {
        m[i] = g_pm[i * MTOT + row];
        lpart[i] = g_pl[i * MTOT + row];
        M = fmaxf(M, m[i]);
    }
    float L = 0.f, w[NSPLIT];
#pragma unroll
    for (int i = 0; i < NSPLIT; i++) {
        w[i] = exp2f(m[i] - M);
        L += w[i] * lpart[i];
    }
    float inv = 1.0f / L;
    float c0 = 0.f, c1 = 0.f;
#pragma unroll
    for (int i = 0; i < NSPLIT; i++) {
        float2 ov = *(const float2*)&g_po[((size_t)i * MTOT + row) * HDIM + col];
        c0 += w[i] * ov.x;
        c1 += w[i] * ov.y;
    }
    *(uint32_t*)&g_ch[row * HDIM + col] = pack2h(c0 * inv, c1 * inv);
}

// ---------------------------------------------------------------------------
// Kernel 4: out = ctx[16384,64] @ Wo_sum[64,1024] + bo (fp16 MMA).
// BM=128, BN=64, K=64. Paired-word smem (pitch 36 u32) -> LDS.64 fragments.
// ---------------------------------------------------------------------------
__global__ __launch_bounds__(256) void outproj_kernel(const float* __restrict__ bo,
                                                      float* __restrict__ out) {
    extern __shared__ uint32_t sm32[];
    uint32_t* As32 = sm32;              // ctx [128][36]
    uint32_t* Bs32 = sm32 + 128 * 36;   // woT [64][36]

    const int tid = threadIdx.x, warp = tid >> 5, lane = tid & 31;
    const int g = lane >> 2, tig = lane & 3;
    const int wm = warp & 3, wn = warp >> 2;
    const int row0 = blockIdx.x * 128, n0 = blockIdx.y * 64;

    const uint32_t* ch32 = (const uint32_t*)g_ch;
    const uint32_t* wo32 = (const uint32_t*)g_woh;

#pragma unroll
    for (int it = 0; it < 16; it++) {
        int id = tid + it * 256;
        int r = id >> 5, gw = id & 31;
        As32[r * 36 + permw(gw)] = ch32[(row0 + r) * 32 + gw];
    }
#pragma unroll
    for (int it = 0; it < 8; it++) {
        int id = tid + it * 256;
        int n = id >> 5, gw = id & 31;
        Bs32[n * 36 + permw(gw)] = wo32[(n0 + n) * 32 + gw];
    }
    __syncthreads();

    float c[2][4][4];
#pragma unroll
    for (int mt = 0; mt < 2; mt++)
#pragma unroll
        for (int nt = 0; nt < 4; nt++)
#pragma unroll
            for (int j = 0; j < 4; j++) c[mt][nt][j] = 0.f;

#pragma unroll
    for (int kc = 0; kc < 4; kc++) {
        uint2 aa[2], ab[2];
#pragma unroll
        for (int mt = 0; mt < 2; mt++) {
            int r = wm * 32 + mt * 16 + g;
            aa[mt] = *(const uint2*)&As32[r * 36 + kc * 8 + 2 * tig];
            ab[mt] = *(const uint2*)&As32[(r + 8) * 36 + kc * 8 + 2 * tig];
        }
#pragma unroll
        for (int nt = 0; nt < 4; nt++) {
            int n = wn * 32 + nt * 8 + g;
            uint2 bb = *(const uint2*)&Bs32[n * 36 + kc * 8 + 2 * tig];
#pragma unroll
            for (int mt = 0; mt < 2; mt++)
                mma_fp16(c[mt][nt], aa[mt].x, ab[mt].x, aa[mt].y, ab[mt].y, bb.x, bb.y);
        }
    }

#pragma unroll
    for (int mt = 0; mt < 2; mt++) {
#pragma unroll
        for (int nt = 0; nt < 4; nt++) {
            int r   = row0 + wm * 32 + mt * 16 + g;
            int col = n0 + wn * 32 + nt * 8 + 2 * tig;
            float bv0 = bo[col], bv1 = bo[col + 1];
            float2 v0 = make_float2(c[mt][nt][0] + bv0, c[mt][nt][1] + bv1);
            float2 v1 = make_float2(c[mt][nt][2] + bv0, c[mt][nt][3] + bv1);
            *(float2*)&out[r * DMODEL + col] = v0;
            *(float2*)&out[(r + 8) * DMODEL + col] = v1;
        }
    }
}

// ---------------------------------------------------------------------------
extern "C" void kernel_launch(void* const* d_in, const int* in_sizes, int n_in,
                              void* d_out, int out_size) {
    const float* query = (const float*)d_in[0];
    const float* key   = (const float*)d_in[1];
    const float* value = (const float*)d_in[2];
    const float* Wq    = (const float*)d_in[3];
    const float* bq    = (const float*)d_in[4];
    const float* Wk    = (const float*)d_in[5];
    const float* bk    = (const float*)d_in[6];
    const float* Wv    = (const float*)d_in[7];
    const float* bv    = (const float*)d_in[8];
    const float* Wo    = (const float*)d_in[9];
    const float* bo    = (const float*)d_in[10];
    float* out = (float*)d_out;

    const int ATTN_SMEM = 3 * 64 * 36 * (int)sizeof(uint32_t);         // 27648
    const int OUTP_SMEM = (128 + 64) * 36 * (int)sizeof(uint32_t);     // 27648

    wosum_kernel<<<256, 256>>>(Wo);
    proj_kernel<<<dim3(128, 3), 256>>>(query, key, value,
                                       Wq, Wk, Wv, bq, bk, bv);
    attn_kernel<<<dim3(SS / 64, BB, NSPLIT), 128, ATTN_SMEM>>>();
    combine_kernel<<<MTOT / 8, 256>>>();
    outproj_kernel<<<dim3(MTOT / 128, DMODEL / 64), 256, OUTP_SMEM>>>(bo, out);
}

// round 10
// speedup vs baseline: 1.0519x; 1.0519x over previous
#include <cuda_runtime.h>
#include <cuda_fp16.h>
#include <cstdint>

// Problem dims
#define BB 8
#define SS 2048
#define DMODEL 1024
#define HDIM 64
#define NHEADS 16
#define MTOT (BB * SS)   // 16384 tokens
#define NSPLIT 4         // KV splits
#define KPS (SS / NSPLIT) // 512 keys per split

// ---------------------------------------------------------------------------
// Scratch (fp16 operands, fp32 partials).
// q,k,ctx: [token][64] row-major.  v: TRANSPOSED [b][dim][s].  wo: [n][d].
// ---------------------------------------------------------------------------
__device__ __half g_qh[MTOT * HDIM];
__device__ __half g_kh[MTOT * HDIM];
__device__ __half g_vh[MTOT * HDIM];     // [b][dim][s]
__device__ __half g_ch[MTOT * HDIM];
__device__ __half g_woh[DMODEL * HDIM];  // [n][d]
// Split-KV partials (fp32, unnormalized o; m,l in log2 domain)
__device__ float g_po[NSPLIT * MTOT * HDIM];
__device__ float g_pm[NSPLIT * MTOT];
__device__ float g_pl[NSPLIT * MTOT];

// ---------------------------------------------------------------------------
// Helpers
// ---------------------------------------------------------------------------
__device__ __forceinline__ void mma_fp16(float c[4],
                                         uint32_t a0, uint32_t a1, uint32_t a2, uint32_t a3,
                                         uint32_t b0, uint32_t b1) {
    asm volatile(
        "mma.sync.aligned.m16n8k16.row.col.f32.f16.f16.f32 "
        "{%0,%1,%2,%3}, {%4,%5,%6,%7}, {%8,%9}, {%0,%1,%2,%3};\n"
        : "+f"(c[0]), "+f"(c[1]), "+f"(c[2]), "+f"(c[3])
        : "r"(a0), "r"(a1), "r"(a2), "r"(a3), "r"(b0), "r"(b1));
}

__device__ __forceinline__ uint32_t pack2h(float x, float y) {
    __half2 h = __floats2half2_rn(x, y);
    return *reinterpret_cast<uint32_t*>(&h);
}

// ---------------------------------------------------------------------------
// Kernel 1: Wo_sum^T[n][d] = sum_h Wo[h*64+d][n]  (fp16)
// ---------------------------------------------------------------------------
__global__ void wosum_kernel(const float* __restrict__ Wo) {
    int idx = blockIdx.x * blockDim.x + threadIdx.x;   // 0..65535
    int d = idx >> 10;
    int n = idx & (DMODEL - 1);
    float s = 0.f;
#pragma unroll
    for (int h = 0; h < NHEADS; h++)
        s += Wo[(h * HDIM + d) * DMODEL + n];
    g_woh[n * HDIM + d] = __float2half_rn(s);
}

// ---------------------------------------------------------------------------
// Kernel 2: fused q/k/v projections (fp16 tensor-core MMA, fp32 accum).
// X[16384,1024] @ W[1024,64] + b.  BM=128, BN=64, BK=32. 256 thr, 8 warps.
// q scaled by 0.125*log2(e) (softmax runs in base-2); v written [b][dim][s].
// (Identical to the 156us round-5 version.)
// ---------------------------------------------------------------------------
#define PP 40   // smem pitch (halves)
#define QSCALE (0.125f * 1.4426950408889634f)
__global__ __launch_bounds__(256) void proj_kernel(
    const float* __restrict__ Xq, const float* __restrict__ Xk, const float* __restrict__ Xv,
    const float* __restrict__ Wq, const float* __restrict__ Wk, const float* __restrict__ Wv,
    const float* __restrict__ bq, const float* __restrict__ bk, const float* __restrict__ bv) {

    const int which = blockIdx.y;
    const float* X;  const float* W;  const float* bias;
    if (which == 0)      { X = Xq; W = Wq; bias = bq; }
    else if (which == 1) { X = Xk; W = Wk; bias = bk; }
    else                 { X = Xv; W = Wv; bias = bv; }

    __shared__ __half Ash[128][PP];
    __shared__ __half Bsh[64][PP];   // W transposed: [n][k]

    const int tid  = threadIdx.x;
    const int warp = tid >> 5, lane = tid & 31;
    const int g = lane >> 2, tig = lane & 3;
    const int wm = warp & 3, wn = warp >> 2;
    const int row0 = blockIdx.x * 128;

    float c[2][4][4];
#pragma unroll
    for (int mt = 0; mt < 2; mt++)
#pragma unroll
        for (int nt = 0; nt < 4; nt++)
#pragma unroll
            for (int j = 0; j < 4; j++) c[mt][nt][j] = 0.f;

    for (int k0 = 0; k0 < DMODEL; k0 += 32) {
        // Stage X tile 128x32
#pragma unroll
        for (int it = 0; it < 4; it++) {
            int id = tid + it * 256;              // 0..1023 float4s
            int r = id >> 3, cg = (id & 7) * 4;
            float4 x4 = *(const float4*)(X + (row0 + r) * DMODEL + k0 + cg);
            *(uint32_t*)&Ash[r][cg]     = pack2h(x4.x, x4.y);
            *(uint32_t*)&Ash[r][cg + 2] = pack2h(x4.z, x4.w);
        }
        // Stage W tile 32x64 transposed into [n][k]
#pragma unroll
        for (int it = 0; it < 2; it++) {
            int id = tid + it * 256;              // 0..511 float4s
            int kr = id >> 4, cg = (id & 15) * 4;
            float4 w4 = *(const float4*)(W + (k0 + kr) * HDIM + cg);
            Bsh[cg + 0][kr] = __float2half_rn(w4.x);
            Bsh[cg + 1][kr] = __float2half_rn(w4.y);
            Bsh[cg + 2][kr] = __float2half_rn(w4.z);
            Bsh[cg + 3][kr] = __float2half_rn(w4.w);
        }
        __syncthreads();

#pragma unroll
        for (int kk = 0; kk < 2; kk++) {
            const int kb = kk * 16;
            uint32_t ah[2][4];
#pragma unroll
            for (int mt = 0; mt < 2; mt++) {
                int r = wm * 32 + mt * 16 + g;
                ah[mt][0] = *(const uint32_t*)&Ash[r    ][kb + 2 * tig];
                ah[mt][1] = *(const uint32_t*)&Ash[r + 8][kb + 2 * tig];
                ah[mt][2] = *(const uint32_t*)&Ash[r    ][kb + 8 + 2 * tig];
                ah[mt][3] = *(const uint32_t*)&Ash[r + 8][kb + 8 + 2 * tig];
            }
#pragma unroll
            for (int nt = 0; nt < 4; nt++) {
                int n = wn * 32 + nt * 8 + g;
                uint32_t bh0 = *(const uint32_t*)&Bsh[n][kb + 2 * tig];
                uint32_t bh1 = *(const uint32_t*)&Bsh[n][kb + 8 + 2 * tig];
#pragma unroll
                for (int mt = 0; mt < 2; mt++)
                    mma_fp16(c[mt][nt], ah[mt][0], ah[mt][1], ah[mt][2], ah[mt][3], bh0, bh1);
            }
        }
        __syncthreads();
    }

    const float scale = (which == 0) ? QSCALE : 1.0f;
    __half* oh = (which == 0) ? g_qh : g_kh;

#pragma unroll
    for (int mt = 0; mt < 2; mt++) {
#pragma unroll
        for (int nt = 0; nt < 4; nt++) {
            int r   = row0 + wm * 32 + mt * 16 + g;
            int col = wn * 32 + nt * 8 + 2 * tig;
            float bv0 = bias[col], bv1 = bias[col + 1];
            float v0 = (c[mt][nt][0] + bv0) * scale;
            float v1 = (c[mt][nt][1] + bv1) * scale;
            float v2 = (c[mt][nt][2] + bv0) * scale;   // row r+8
            float v3 = (c[mt][nt][3] + bv1) * scale;
            if (which < 2) {
                *(uint32_t*)&oh[r * HDIM + col]       = pack2h(v0, v1);
                *(uint32_t*)&oh[(r + 8) * HDIM + col] = pack2h(v2, v3);
            } else {
                // v transposed: [b][dim][s]
                int b = r >> 11, s = r & 2047;
                g_vh[(b * HDIM + col) * SS + s]         = __float2half_rn(v0);
                g_vh[(b * HDIM + col + 1) * SS + s]     = __float2half_rn(v1);
                g_vh[(b * HDIM + col) * SS + s + 8]     = __float2half_rn(v2);
                g_vh[(b * HDIM + col + 1) * SS + s + 8] = __float2half_rn(v3);
            }
        }
    }
}

// ---------------------------------------------------------------------------
// Kernel 3: split-KV flash attention (fp16 tensor cores).
// grid (S/128, B, NSPLIT); block 256 (8 warps, warp owns 16 q-rows).
// 128 q-rows per block: K/V staging amortized over 2x warps vs round 5.
// Q fragments hoisted into registers before the kt loop (loop-invariant).
// Deferred per-lane l accumulation (reduced once at epilogue).
// Plain round-5 smem layout (pitch 36 u32, LDS.32 conflict-free).
// ---------------------------------------------------------------------------
__global__ __launch_bounds__(256, 2) void attn_kernel() {
    extern __shared__ uint32_t sm32[];
    uint32_t* Qs = sm32;                 // [128][36]
    uint32_t* Ks = sm32 + 128 * 36;      // [64][36]
    uint32_t* Vs = sm32 + (128 + 64) * 36; // [64][36]

    const int tid = threadIdx.x, warp = tid >> 5, lane = tid & 31;
    const int g = lane >> 2, tig = lane & 3;
    const int bq = blockIdx.x, b = blockIdx.y, split = blockIdx.z;
    const int t0 = b * SS + bq * 128;
    const int kt0 = split * (KPS / 64);

    const uint32_t* qb32 = (const uint32_t*)g_qh;
    const uint32_t* kb32 = (const uint32_t*)(g_kh + (size_t)b * SS * HDIM);
    const uint32_t* vb32 = (const uint32_t*)(g_vh + (size_t)b * HDIM * SS);

    // Stage Q tile (128 rows x 32 u32)
#pragma unroll
    for (int it = 0; it < 16; it++) {
        int id = tid + it * 256;
        int r = id >> 5, dp = id & 31;
        Qs[r * 36 + dp] = qb32[(t0 + r) * 32 + dp];
    }
    __syncthreads();

    // Hoist Q fragments (loop-invariant across kt): 16 u32 regs
    const int qr = warp * 16 + g;
    uint32_t qf[4][4];
#pragma unroll
    for (int kc = 0; kc < 4; kc++) {
        qf[kc][0] = Qs[qr * 36 + kc * 8 + tig];
        qf[kc][1] = Qs[(qr + 8) * 36 + kc * 8 + tig];
        qf[kc][2] = Qs[qr * 36 + kc * 8 + 4 + tig];
        qf[kc][3] = Qs[(qr + 8) * 36 + kc * 8 + 4 + tig];
    }

    float m0 = -1e30f, m1 = -1e30f, l0 = 0.f, l1 = 0.f;   // l: per-lane partial
    float o[8][4];
#pragma unroll
    for (int nt = 0; nt < 8; nt++)
#pragma unroll
        for (int j = 0; j < 4; j++) o[nt][j] = 0.f;

    for (int kt = kt0; kt < kt0 + KPS / 64; kt++) {
        // Stage K and V tiles (64 rows x 32 u32 each), 8 u32 per thread each
#pragma unroll
        for (int it = 0; it < 8; it++) {
            int id = tid + it * 256;
            int r = id >> 5, dp = id & 31;
            Ks[r * 36 + dp] = kb32[(kt * 64 + r) * 32 + dp];
            Vs[r * 36 + dp] = vb32[r * 1024 + kt * 32 + dp];
        }
        __syncthreads();

        // S = Q K^T
        float s[8][4];
#pragma unroll
        for (int nt = 0; nt < 8; nt++)
#pragma unroll
            for (int j = 0; j < 4; j++) s[nt][j] = 0.f;

#pragma unroll
        for (int kc = 0; kc < 4; kc++) {
#pragma unroll
            for (int nt = 0; nt < 8; nt++) {
                int n = nt * 8 + g;
                uint32_t kf0 = Ks[n * 36 + kc * 8 + tig];
                uint32_t kf1 = Ks[n * 36 + kc * 8 + 4 + tig];
                mma_fp16(s[nt], qf[kc][0], qf[kc][1], qf[kc][2], qf[kc][3], kf0, kf1);
            }
        }

        // Online softmax, base-2 domain. Max reduced across tig; l deferred.
        float mt0 = -1e30f, mt1 = -1e30f;
#pragma unroll
        for (int nt = 0; nt < 8; nt++) {
            mt0 = fmaxf(mt0, fmaxf(s[nt][0], s[nt][1]));
            mt1 = fmaxf(mt1, fmaxf(s[nt][2], s[nt][3]));
        }
        mt0 = fmaxf(mt0, __shfl_xor_sync(0xffffffffu, mt0, 1));
        mt0 = fmaxf(mt0, __shfl_xor_sync(0xffffffffu, mt0, 2));
        mt1 = fmaxf(mt1, __shfl_xor_sync(0xffffffffu, mt1, 1));
        mt1 = fmaxf(mt1, __shfl_xor_sync(0xffffffffu, mt1, 2));
        float mn0 = fmaxf(m0, mt0), mn1 = fmaxf(m1, mt1);
        float cr0 = exp2f(m0 - mn0), cr1 = exp2f(m1 - mn1);
        m0 = mn0; m1 = mn1;
        float ls0 = 0.f, ls1 = 0.f;
#pragma unroll
        for (int nt = 0; nt < 8; nt++) {
            s[nt][0] = exp2f(s[nt][0] - mn0); ls0 += s[nt][0];
            s[nt][1] = exp2f(s[nt][1] - mn0); ls0 += s[nt][1];
            s[nt][2] = exp2f(s[nt][2] - mn1); ls1 += s[nt][2];
            s[nt][3] = exp2f(s[nt][3] - mn1); ls1 += s[nt][3];
        }
        l0 = l0 * cr0 + ls0;      // per-lane partial (cr uniform across tig)
        l1 = l1 * cr1 + ls1;
#pragma unroll
        for (int nt = 0; nt < 8; nt++) {
            o[nt][0] *= cr0; o[nt][1] *= cr0;
            o[nt][2] *= cr1; o[nt][3] *= cr1;
        }

        // ctx += P V  (P fragments straight from accumulators)
#pragma unroll
        for (int kc = 0; kc < 4; kc++) {
            uint32_t ph0 = pack2h(s[2 * kc][0],     s[2 * kc][1]);
            uint32_t ph1 = pack2h(s[2 * kc][2],     s[2 * kc][3]);
            uint32_t ph2 = pack2h(s[2 * kc + 1][0], s[2 * kc + 1][1]);
            uint32_t ph3 = pack2h(s[2 * kc + 1][2], s[2 * kc + 1][3]);
#pragma unroll
            for (int nt = 0; nt < 8; nt++) {
                int n = nt * 8 + g;
                uint32_t vf0 = Vs[n * 36 + kc * 8 + tig];
                uint32_t vf1 = Vs[n * 36 + kc * 8 + 4 + tig];
                mma_fp16(o[nt], ph0, ph1, ph2, ph3, vf0, vf1);
            }
        }
        __syncthreads();
    }

    // Final l reduction across the 4 tig lanes
    l0 += __shfl_xor_sync(0xffffffffu, l0, 1);
    l0 += __shfl_xor_sync(0xffffffffu, l0, 2);
    l1 += __shfl_xor_sync(0xffffffffu, l1, 1);
    l1 += __shfl_xor_sync(0xffffffffu, l1, 2);

    // Write unnormalized partials
    const int r = t0 + warp * 16 + g;
    float* po = g_po + (size_t)split * MTOT * HDIM;
#pragma unroll
    for (int nt = 0; nt < 8; nt++) {
        int col = nt * 8 + 2 * tig;
        *(float2*)&po[r * HDIM + col]       = make_float2(o[nt][0], o[nt][1]);
        *(float2*)&po[(r + 8) * HDIM + col] = make_float2(o[nt][2], o[nt][3]);
    }
    if (tig == 0) {
        g_pm[split * MTOT + r]     = m0;
        g_pm[split * MTOT + r + 8] = m1;
        g_pl[split * MTOT + r]     = l0;
        g_pl[split * MTOT + r + 8] = l1;
    }
}

// ---------------------------------------------------------------------------
// Kernel 3b: combine split-KV partials -> ctx (fp16).
// ---------------------------------------------------------------------------
__global__ __launch_bounds__(256) void combine_kernel() {
    const int warp = threadIdx.x >> 5, lane = threadIdx.x & 31;
    const int row = blockIdx.x * 8 + warp;
    const int col = lane * 2;

    float m[NSPLIT], lpart[NSPLIT];
    float M = -1e30f;
#pragma unroll
    for (int i = 0; i < NSPLIT; i++) {
        m[i] = g_pm[i * MTOT + row];
        lpart[i] = g_pl[i * MTOT + row];
        M = fmaxf(M, m[i]);
    }
    float L = 0.f, w[NSPLIT];
#pragma unroll
    for (int i = 0; i < NSPLIT; i++) {
        w[i] = exp2f(m[i] - M);
        L += w[i] * lpart[i];
    }
    float inv = 1.0f / L;
    float c0 = 0.f, c1 = 0.f;
#pragma unroll
    for (int i = 0; i < NSPLIT; i++) {
        float2 ov = *(const float2*)&g_po[((size_t)i * MTOT + row) * HDIM + col];
        c0 += w[i] * ov.x;
        c1 += w[i] * ov.y;
    }
    *(uint32_t*)&g_ch[row * HDIM + col] = pack2h(c0 * inv, c1 * inv);
}

// ---------------------------------------------------------------------------
// Kernel 4: out = ctx[16384,64] @ Wo_sum[64,1024] + bo (fp16 MMA).
// BM=128, BN=64, K=64.  (Identical to the 156us round-5 version.)
// ---------------------------------------------------------------------------
#define AP 72   // smem pitch (halves)
__global__ __launch_bounds__(256) void outproj_kernel(const float* __restrict__ bo,
                                                      float* __restrict__ out) {
    extern __shared__ __half smh[];
    __half* Ash = smh;              // ctx [128][AP]
    __half* Bsh = smh + 128 * AP;   // woT [64][AP]

    const int tid = threadIdx.x, warp = tid >> 5, lane = tid & 31;
    const int g = lane >> 2, tig = lane & 3;
    const int wm = warp & 3, wn = warp >> 2;
    const int row0 = blockIdx.x * 128, n0 = blockIdx.y * 64;

#pragma unroll
    for (int it = 0; it < 16; it++) {
        int id = tid + it * 256;                  // 0..4095 u32s
        int r = id >> 5, dp = (id & 31) * 2;
        *(uint32_t*)&Ash[r * AP + dp] = *(const uint32_t*)&g_ch[(row0 + r) * HDIM + dp];
    }
#pragma unroll
    for (int it = 0; it < 8; it++) {
        int id = tid + it * 256;                  // 0..2047 u32s
        int n = id >> 5, dp = (id & 31) * 2;
        *(uint32_t*)&Bsh[n * AP + dp] = *(const uint32_t*)&g_woh[(n0 + n) * HDIM + dp];
    }
    __syncthreads();

    float c[2][4][4];
#pragma unroll
    for (int mt = 0; mt < 2; mt++)
#pragma unroll
        for (int nt = 0; nt < 4; nt++)
#pragma unroll
            for (int j = 0; j < 4; j++) c[mt][nt][j] = 0.f;

#pragma unroll
    for (int kc = 0; kc < 4; kc++) {
        const int kb = kc * 16;
        uint32_t ah[2][4];
#pragma unroll
        for (int mt = 0; mt < 2; mt++) {
            int r = wm * 32 + mt * 16 + g;
            ah[mt][0] = *(const uint32_t*)&Ash[r * AP + kb + 2 * tig];
            ah[mt][1] = *(const uint32_t*)&Ash[(r + 8) * AP + kb + 2 * tig];
            ah[mt][2] = *(const uint32_t*)&Ash[r * AP + kb + 8 + 2 * tig];
            ah[mt][3] = *(const uint32_t*)&Ash[(r + 8) * AP + kb + 8 + 2 * tig];
        }
#pragma unroll
        for (int nt = 0; nt < 4; nt++) {
            int n = wn * 32 + nt * 8 + g;
            uint32_t bh0 = *(const uint32_t*)&Bsh[n * AP + kb + 2 * tig];
            uint32_t bh1 = *(const uint32_t*)&Bsh[n * AP + kb + 8 + 2 * tig];
#pragma unroll
            for (int mt = 0; mt < 2; mt++)
                mma_fp16(c[mt][nt], ah[mt][0], ah[mt][1], ah[mt][2], ah[mt][3], bh0, bh1);
        }
    }

#pragma unroll
    for (int mt = 0; mt < 2; mt++) {
#pragma unroll
        for (int nt = 0; nt < 4; nt++) {
            int r   = row0 + wm * 32 + mt * 16 + g;
            int col = n0 + wn * 32 + nt * 8 + 2 * tig;
            float bv0 = bo[col], bv1 = bo[col + 1];
            float2 v0 = make_float2(c[mt][nt][0] + bv0, c[mt][nt][1] + bv1);
            float2 v1 = make_float2(c[mt][nt][2] + bv0, c[mt][nt][3] + bv1);
            *(float2*)&out[r * DMODEL + col] = v0;
            *(float2*)&out[(r + 8) * DMODEL + col] = v1;
        }
    }
}

// ---------------------------------------------------------------------------
extern "C" void kernel_launch(void* const* d_in, const int* in_sizes, int n_in,
                              void* d_out, int out_size) {
    const float* query = (const float*)d_in[0];
    const float* key   = (const float*)d_in[1];
    const float* value = (const float*)d_in[2];
    const float* Wq    = (const float*)d_in[3];
    const float* bq    = (const float*)d_in[4];
    const float* Wk    = (const float*)d_in[5];
    const float* bk    = (const float*)d_in[6];
    const float* Wv    = (const float*)d_in[7];
    const float* bv    = (const float*)d_in[8];
    const float* Wo    = (const float*)d_in[9];
    const float* bo    = (const float*)d_in[10];
    float* out = (float*)d_out;

    const int ATTN_SMEM = (128 + 64 + 64) * 36 * (int)sizeof(uint32_t); // 36864
    const int OUTP_SMEM = (128 + 64) * AP * (int)sizeof(__half);        // 27648

    wosum_kernel<<<256, 256>>>(Wo);
    proj_kernel<<<dim3(128, 3), 256>>>(query, key, value,
                                       Wq, Wk, Wv, bq, bk, bv);
    attn_kernel<<<dim3(SS / 128, BB, NSPLIT), 256, ATTN_SMEM>>>();
    combine_kernel<<<MTOT / 8, 256>>>();
    outproj_kernel<<<dim3(MTOT / 128, DMODEL / 64), 256, OUTP_SMEM>>>(bo, out);
}

// round 13
// speedup vs baseline: 1.0644x; 1.0118x over previous
#include <cuda_runtime.h>
#include <cuda_fp16.h>
#include <cstdint>

// Problem dims
#define BB 8
#define SS 2048
#define DMODEL 1024
#define HDIM 64
#define NHEADS 16
#define MTOT (BB * SS)   // 16384 tokens
#define NSPLIT 4         // KV splits
#define KPS (SS / NSPLIT) // 512 keys per split

// ---------------------------------------------------------------------------
// Scratch (fp16 operands, fp32 partials).
// q,k,ctx: [token][64] row-major.  v: TRANSPOSED [b][dim][s].  wo: [n][d].
// ---------------------------------------------------------------------------
__device__ __half g_qh[MTOT * HDIM];
__device__ __half g_kh[MTOT * HDIM];
__device__ __half g_vh[MTOT * HDIM];     // [b][dim][s]
__device__ __half g_ch[MTOT * HDIM];
__device__ __half g_woh[DMODEL * HDIM];  // [n][d]
// Split-KV partials (fp32, unnormalized o; m,l in log2 domain)
__device__ float g_po[NSPLIT * MTOT * HDIM];
__device__ float g_pm[NSPLIT * MTOT];
__device__ float g_pl[NSPLIT * MTOT];

// ---------------------------------------------------------------------------
// Helpers
// ---------------------------------------------------------------------------
__device__ __forceinline__ void mma_fp16(float c[4],
                                         uint32_t a0, uint32_t a1, uint32_t a2, uint32_t a3,
                                         uint32_t b0, uint32_t b1) {
    asm volatile(
        "mma.sync.aligned.m16n8k16.row.col.f32.f16.f16.f32 "
        "{%0,%1,%2,%3}, {%4,%5,%6,%7}, {%8,%9}, {%0,%1,%2,%3};\n"
        : "+f"(c[0]), "+f"(c[1]), "+f"(c[2]), "+f"(c[3])
        : "r"(a0), "r"(a1), "r"(a2), "r"(a3), "r"(b0), "r"(b1));
}

__device__ __forceinline__ uint32_t pack2h(float x, float y) {
    __half2 h = __floats2half2_rn(x, y);
    return *reinterpret_cast<uint32_t*>(&h);
}

// ---------------------------------------------------------------------------
// Kernel 1: Wo_sum^T[n][d] = sum_h Wo[h*64+d][n]  (fp16)
// ---------------------------------------------------------------------------
__global__ void wosum_kernel(const float* __restrict__ Wo) {
    int idx = blockIdx.x * blockDim.x + threadIdx.x;   // 0..65535
    int d = idx >> 10;
    int n = idx & (DMODEL - 1);
    float s = 0.f;
#pragma unroll
    for (int h = 0; h < NHEADS; h++)
        s += Wo[(h * HDIM + d) * DMODEL + n];
    g_woh[n * HDIM + d] = __float2half_rn(s);
}

// ---------------------------------------------------------------------------
// Kernel 2: fused q/k/v projections (fp16 MMA, fp32 accum).
// X[16384,1024] @ W[1024,64] + b.  BM=128, BN=64, BK=64. 256 thr, 8 warps.
// Register double-buffered: tile k+1's global loads issue before the MMA
// section of tile k, hiding DRAM latency. Fragment layout = outproj's
// proven pitch-72 pattern (conflict-free).
// q scaled by 0.125*log2(e) (softmax runs in base-2); v written [b][dim][s].
// ---------------------------------------------------------------------------
#define AP 72   // smem pitch (halves)
#define QSCALE (0.125f * 1.4426950408889634f)
__global__ __launch_bounds__(256) void proj_kernel(
    const float* __restrict__ Xq, const float* __restrict__ Xk, const float* __restrict__ Xv,
    const float* __restrict__ Wq, const float* __restrict__ Wk, const float* __restrict__ Wv,
    const float* __restrict__ bq, const float* __restrict__ bk, const float* __restrict__ bv) {

    const int which = blockIdx.y;
    const float* X;  const float* W;  const float* bias;
    if (which == 0)      { X = Xq; W = Wq; bias = bq; }
    else if (which == 1) { X = Xk; W = Wk; bias = bk; }
    else                 { X = Xv; W = Wv; bias = bv; }

    __shared__ __half Ash[128][AP];
    __shared__ __half Bsh[64][AP];   // W transposed: [n][k]

    const int tid  = threadIdx.x;
    const int warp = tid >> 5, lane = tid & 31;
    const int g = lane >> 2, tig = lane & 3;
    const int wm = warp & 3, wn = warp >> 2;
    const int row0 = blockIdx.x * 128;

    float c[2][4][4];
#pragma unroll
    for (int mt = 0; mt < 2; mt++)
#pragma unroll
        for (int nt = 0; nt < 4; nt++)
#pragma unroll
            for (int j = 0; j < 4; j++) c[mt][nt][j] = 0.f;

    // Prime the register buffer with tile 0 (A: 8 float4/thr, B: 4 float4/thr)
    float4 xa[8], wb[4];
#pragma unroll
    for (int it = 0; it < 8; it++) {
        int id = tid + it * 256;              // 0..2047 float4s
        int r = id >> 4, cg = (id & 15) * 4;
        xa[it] = *(const float4*)(X + (row0 + r) * DMODEL + cg);
    }
#pragma unroll
    for (int it = 0; it < 4; it++) {
        int id = tid + it * 256;              // 0..1023 float4s
        int kr = id >> 4, cg = (id & 15) * 4;
        wb[it] = *(const float4*)(W + kr * HDIM + cg);
    }

    for (int k0 = 0; k0 < DMODEL; k0 += 64) {
        // Drain register buffer -> smem (fp32 -> fp16 conversion here)
#pragma unroll
        for (int it = 0; it < 8; it++) {
            int id = tid + it * 256;
            int r = id >> 4, cg = (id & 15) * 4;
            *(uint32_t*)&Ash[r][cg]     = pack2h(xa[it].x, xa[it].y);
            *(uint32_t*)&Ash[r][cg + 2] = pack2h(xa[it].z, xa[it].w);
        }
#pragma unroll
        for (int it = 0; it < 4; it++) {
            int id = tid + it * 256;
            int kr = id >> 4, cg = (id & 15) * 4;
            Bsh[cg + 0][kr] = __float2half_rn(wb[it].x);
            Bsh[cg + 1][kr] = __float2half_rn(wb[it].y);
            Bsh[cg + 2][kr] = __float2half_rn(wb[it].z);
            Bsh[cg + 3][kr] = __float2half_rn(wb[it].w);
        }
        __syncthreads();

        // Issue next tile's global loads now; consumed after next sync ->
        // DRAM latency overlaps the MMA section below.
        if (k0 + 64 < DMODEL) {
#pragma unroll
            for (int it = 0; it < 8; it++) {
                int id = tid + it * 256;
                int r = id >> 4, cg = (id & 15) * 4;
                xa[it] = *(const float4*)(X + (row0 + r) * DMODEL + k0 + 64 + cg);
            }
#pragma unroll
            for (int it = 0; it < 4; it++) {
                int id = tid + it * 256;
                int kr = id >> 4, cg = (id & 15) * 4;
                wb[it] = *(const float4*)(W + (k0 + 64 + kr) * HDIM + cg);
            }
        }

#pragma unroll
        for (int kc = 0; kc < 4; kc++) {
            const int kb = kc * 16;
            uint32_t ah[2][4];
#pragma unroll
            for (int mt = 0; mt < 2; mt++) {
                int r = wm * 32 + mt * 16 + g;
                ah[mt][0] = *(const uint32_t*)&Ash[r    ][kb + 2 * tig];
                ah[mt][1] = *(const uint32_t*)&Ash[r + 8][kb + 2 * tig];
                ah[mt][2] = *(const uint32_t*)&Ash[r    ][kb + 8 + 2 * tig];
                ah[mt][3] = *(const uint32_t*)&Ash[r + 8][kb + 8 + 2 * tig];
            }
#pragma unroll
            for (int nt = 0; nt < 4; nt++) {
                int n = wn * 32 + nt * 8 + g;
                uint32_t bh0 = *(const uint32_t*)&Bsh[n][kb + 2 * tig];
                uint32_t bh1 = *(const uint32_t*)&Bsh[n][kb + 8 + 2 * tig];
#pragma unroll
                for (int mt = 0; mt < 2; mt++)
                    mma_fp16(c[mt][nt], ah[mt][0], ah[mt][1], ah[mt][2], ah[mt][3], bh0, bh1);
            }
        }
        __syncthreads();
    }

    const float scale = (which == 0) ? QSCALE : 1.0f;
    __half* oh = (which == 0) ? g_qh : g_kh;

#pragma unroll
    for (int mt = 0; mt < 2; mt++) {
#pragma unroll
        for (int nt = 0; nt < 4; nt++) {
            int r   = row0 + wm * 32 + mt * 16 + g;
            int col = wn * 32 + nt * 8 + 2 * tig;
            float bv0 = bias[col], bv1 = bias[col + 1];
            float v0 = (c[mt][nt][0] + bv0) * scale;
            float v1 = (c[mt][nt][1] + bv1) * scale;
            float v2 = (c[mt][nt][2] + bv0) * scale;   // row r+8
            float v3 = (c[mt][nt][3] + bv1) * scale;
            if (which < 2) {
                *(uint32_t*)&oh[r * HDIM + col]       = pack2h(v0, v1);
                *(uint32_t*)&oh[(r + 8) * HDIM + col] = pack2h(v2, v3);
            } else {
                // v transposed: [b][dim][s]
                int b = r >> 11, s = r & 2047;
                g_vh[(b * HDIM + col) * SS + s]         = __float2half_rn(v0);
                g_vh[(b * HDIM + col + 1) * SS + s]     = __float2half_rn(v1);
                g_vh[(b * HDIM + col) * SS + s + 8]     = __float2half_rn(v2);
                g_vh[(b * HDIM + col + 1) * SS + s + 8] = __float2half_rn(v3);
            }
        }
    }
}

// ---------------------------------------------------------------------------
// Kernel 3: split-KV flash attention (fp16 tensor cores).
// grid (S/128, B, NSPLIT); block 256 (8 warps, warp owns 16 q-rows).
// (Identical to the 155.9us round-10 version.)
// ---------------------------------------------------------------------------
__global__ __launch_bounds__(256, 2) void attn_kernel() {
    extern __shared__ uint32_t sm32[];
    uint32_t* Qs = sm32;                 // [128][36]
    uint32_t* Ks = sm32 + 128 * 36;      // [64][36]
    uint32_t* Vs = sm32 + (128 + 64) * 36; // [64][36]

    const int tid = threadIdx.x, warp = tid >> 5, lane = tid & 31;
    const int g = lane >> 2, tig = lane & 3;
    const int bq = blockIdx.x, b = blockIdx.y, split = blockIdx.z;
    const int t0 = b * SS + bq * 128;
    const int kt0 = split * (KPS / 64);

    const uint32_t* qb32 = (const uint32_t*)g_qh;
    const uint32_t* kb32 = (const uint32_t*)(g_kh + (size_t)b * SS * HDIM);
    const uint32_t* vb32 = (const uint32_t*)(g_vh + (size_t)b * HDIM * SS);

    // Stage Q tile (128 rows x 32 u32)
#pragma unroll
    for (int it = 0; it < 16; it++) {
        int id = tid + it * 256;
        int r = id >> 5, dp = id & 31;
        Qs[r * 36 + dp] = qb32[(t0 + r) * 32 + dp];
    }
    __syncthreads();

    // Hoist Q fragments (loop-invariant across kt): 16 u32 regs
    const int qr = warp * 16 + g;
    uint32_t qf[4][4];
#pragma unroll
    for (int kc = 0; kc < 4; kc++) {
        qf[kc][0] = Qs[qr * 36 + kc * 8 + tig];
        qf[kc][1] = Qs[(qr + 8) * 36 + kc * 8 + tig];
        qf[kc][2] = Qs[qr * 36 + kc * 8 + 4 + tig];
        qf[kc][3] = Qs[(qr + 8) * 36 + kc * 8 + 4 + tig];
    }

    float m0 = -1e30f, m1 = -1e30f, l0 = 0.f, l1 = 0.f;   // l: per-lane partial
    float o[8][4];
#pragma unroll
    for (int nt = 0; nt < 8; nt++)
#pragma unroll
        for (int j = 0; j < 4; j++) o[nt][j] = 0.f;

    for (int kt = kt0; kt < kt0 + KPS / 64; kt++) {
        // Stage K and V tiles (64 rows x 32 u32 each), 8 u32 per thread each
#pragma unroll
        for (int it = 0; it < 8; it++) {
            int id = tid + it * 256;
            int r = id >> 5, dp = id & 31;
            Ks[r * 36 + dp] = kb32[(kt * 64 + r) * 32 + dp];
            Vs[r * 36 + dp] = vb32[r * 1024 + kt * 32 + dp];
        }
        __syncthreads();

        // S = Q K^T
        float s[8][4];
#pragma unroll
        for (int nt = 0; nt < 8; nt++)
#pragma unroll
            for (int j = 0; j < 4; j++) s[nt][j] = 0.f;

#pragma unroll
        for (int kc = 0; kc < 4; kc++) {
#pragma unroll
            for (int nt = 0; nt < 8; nt++) {
                int n = nt * 8 + g;
                uint32_t kf0 = Ks[n * 36 + kc * 8 + tig];
                uint32_t kf1 = Ks[n * 36 + kc * 8 + 4 + tig];
                mma_fp16(s[nt], qf[kc][0], qf[kc][1], qf[kc][2], qf[kc][3], kf0, kf1);
            }
        }

        // Online softmax, base-2 domain. Max reduced across tig; l deferred.
        float mt0 = -1e30f, mt1 = -1e30f;
#pragma unroll
        for (int nt = 0; nt < 8; nt++) {
            mt0 = fmaxf(mt0, fmaxf(s[nt][0], s[nt][1]));
            mt1 = fmaxf(mt1, fmaxf(s[nt][2], s[nt][3]));
        }
        mt0 = fmaxf(mt0, __shfl_xor_sync(0xffffffffu, mt0, 1));
        mt0 = fmaxf(mt0, __shfl_xor_sync(0xffffffffu, mt0, 2));
        mt1 = fmaxf(mt1, __shfl_xor_sync(0xffffffffu, mt1, 1));
        mt1 = fmaxf(mt1, __shfl_xor_sync(0xffffffffu, mt1, 2));
        float mn0 = fmaxf(m0, mt0), mn1 = fmaxf(m1, mt1);
        float cr0 = exp2f(m0 - mn0), cr1 = exp2f(m1 - mn1);
        m0 = mn0; m1 = mn1;
        float ls0 = 0.f, ls1 = 0.f;
#pragma unroll
        for (int nt = 0; nt < 8; nt++) {
            s[nt][0] = exp2f(s[nt][0] - mn0); ls0 += s[nt][0];
            s[nt][1] = exp2f(s[nt][1] - mn0); ls0 += s[nt][1];
            s[nt][2] = exp2f(s[nt][2] - mn1); ls1 += s[nt][2];
            s[nt][3] = exp2f(s[nt][3] - mn1); ls1 += s[nt][3];
        }
        l0 = l0 * cr0 + ls0;      // per-lane partial (cr uniform across tig)
        l1 = l1 * cr1 + ls1;
#pragma unroll
        for (int nt = 0; nt < 8; nt++) {
            o[nt][0] *= cr0; o[nt][1] *= cr0;
            o[nt][2] *= cr1; o[nt][3] *= cr1;
        }

        // ctx += P V  (P fragments straight from accumulators)
#pragma unroll
        for (int kc = 0; kc < 4; kc++) {
            uint32_t ph0 = pack2h(s[2 * kc][0],     s[2 * kc][1]);
            uint32_t ph1 = pack2h(s[2 * kc][2],     s[2 * kc][3]);
            uint32_t ph2 = pack2h(s[2 * kc + 1][0], s[2 * kc + 1][1]);
            uint32_t ph3 = pack2h(s[2 * kc + 1][2], s[2 * kc + 1][3]);
#pragma unroll
            for (int nt = 0; nt < 8; nt++) {
                int n = nt * 8 + g;
                uint32_t vf0 = Vs[n * 36 + kc * 8 + tig];
                uint32_t vf1 = Vs[n * 36 + kc * 8 + 4 + tig];
                mma_fp16(o[nt], ph0, ph1, ph2, ph3, vf0, vf1);
            }
        }
        __syncthreads();
    }

    // Final l reduction across the 4 tig lanes
    l0 += __shfl_xor_sync(0xffffffffu, l0, 1);
    l0 += __shfl_xor_sync(0xffffffffu, l0, 2);
    l1 += __shfl_xor_sync(0xffffffffu, l1, 1);
    l1 += __shfl_xor_sync(0xffffffffu, l1, 2);

    // Write unnormalized partials
    const int r = t0 + warp * 16 + g;
    float* po = g_po + (size_t)split * MTOT * HDIM;
#pragma unroll
    for (int nt = 0; nt < 8; nt++) {
        int col = nt * 8 + 2 * tig;
        *(float2*)&po[r * HDIM + col]       = make_float2(o[nt][0], o[nt][1]);
        *(float2*)&po[(r + 8) * HDIM + col] = make_float2(o[nt][2], o[nt][3]);
    }
    if (tig == 0) {
        g_pm[split * MTOT + r]     = m0;
        g_pm[split * MTOT + r + 8] = m1;
        g_pl[split * MTOT + r]     = l0;
        g_pl[split * MTOT + r + 8] = l1;
    }
}

// ---------------------------------------------------------------------------
// Kernel 3b: combine split-KV partials -> ctx (fp16).
// ---------------------------------------------------------------------------
__global__ __launch_bounds__(256) void combine_kernel() {
    const int warp = threadIdx.x >> 5, lane = threadIdx.x & 31;
    const int row = blockIdx.x * 8 + warp;
    const int col = lane * 2;

    float m[NSPLIT], lpart[NSPLIT];
    float M = -1e30f;
#pragma unroll
    for (int i = 0; i < NSPLIT; i++) {
        m[i] = g_pm[i * MTOT + row];
        lpart[i] = g_pl[i * MTOT + row];
        M = fmaxf(M, m[i]);
    }
    float L = 0.f, w[NSPLIT];
#pragma unroll
    for (int i = 0; i < NSPLIT; i++) {
        w[i] = exp2f(m[i] - M);
        L += w[i] * lpart[i];
    }
    float inv = 1.0f / L;
    float c0 = 0.f, c1 = 0.f;
#pragma unroll
    for (int i = 0; i < NSPLIT; i++) {
        float2 ov = *(const float2*)&g_po[((size_t)i * MTOT + row) * HDIM + col];
        c0 += w[i] * ov.x;
        c1 += w[i] * ov.y;
    }
    *(uint32_t*)&g_ch[row * HDIM + col] = pack2h(c0 * inv, c1 * inv);
}

// ---------------------------------------------------------------------------
// Kernel 4: out = ctx[16384,64] @ Wo_sum[64,1024] + bo (fp16 MMA).
// BM=128, BN=64, K=64.  (Identical to the round-5/10 version.)
// ---------------------------------------------------------------------------
__global__ __launch_bounds__(256) void outproj_kernel(const float* __restrict__ bo,
                                                      float* __restrict__ out) {
    extern __shared__ __half smh[];
    __half* Ash = smh;              // ctx [128][AP]
    __half* Bsh = smh + 128 * AP;   // woT [64][AP]

    const int tid = threadIdx.x, warp = tid >> 5, lane = tid & 31;
    const int g = lane >> 2, tig = lane & 3;
    const int wm = warp & 3, wn = warp >> 2;
    const int row0 = blockIdx.x * 128, n0 = blockIdx.y * 64;

#pragma unroll
    for (int it = 0; it < 16; it++) {
        int id = tid + it * 256;                  // 0..4095 u32s
        int r = id >> 5, dp = (id & 31) * 2;
        *(uint32_t*)&Ash[r * AP + dp] = *(const uint32_t*)&g_ch[(row0 + r) * HDIM + dp];
    }
#pragma unroll
    for (int it = 0; it < 8; it++) {
        int id = tid + it * 256;                  // 0..2047 u32s
        int n = id >> 5, dp = (id & 31) * 2;
        *(uint32_t*)&Bsh[n * AP + dp] = *(const uint32_t*)&g_woh[(n0 + n) * HDIM + dp];
    }
    __syncthreads();

    float c[2][4][4];
#pragma unroll
    for (int mt = 0; mt < 2; mt++)
#pragma unroll
        for (int nt = 0; nt < 4; nt++)
#pragma unroll
            for (int j = 0; j < 4; j++) c[mt][nt][j] = 0.f;

#pragma unroll
    for (int kc = 0; kc < 4; kc++) {
        const int kb = kc * 16;
        uint32_t ah[2][4];
#pragma unroll
        for (int mt = 0; mt < 2; mt++) {
            int r = wm * 32 + mt * 16 + g;
            ah[mt][0] = *(const uint32_t*)&Ash[r * AP + kb + 2 * tig];
            ah[mt][1] = *(const uint32_t*)&Ash[(r + 8) * AP + kb + 2 * tig];
            ah[mt][2] = *(const uint32_t*)&Ash[r * AP + kb + 8 + 2 * tig];
            ah[mt][3] = *(const uint32_t*)&Ash[(r + 8) * AP + kb + 8 + 2 * tig];
        }
#pragma unroll
        for (int nt = 0; nt < 4; nt++) {
            int n = wn * 32 + nt * 8 + g;
            uint32_t bh0 = *(const uint32_t*)&Bsh[n * AP + kb + 2 * tig];
            uint32_t bh1 = *(const uint32_t*)&Bsh[n * AP + kb + 8 + 2 * tig];
#pragma unroll
            for (int mt = 0; mt < 2; mt++)
                mma_fp16(c[mt][nt], ah[mt][0], ah[mt][1], ah[mt][2], ah[mt][3], bh0, bh1);
        }
    }

#pragma unroll
    for (int mt = 0; mt < 2; mt++) {
#pragma unroll
        for (int nt = 0; nt < 4; nt++) {
            int r   = row0 + wm * 32 + mt * 16 + g;
            int col = n0 + wn * 32 + nt * 8 + 2 * tig;
            float bv0 = bo[col], bv1 = bo[col + 1];
            float2 v0 = make_float2(c[mt][nt][0] + bv0, c[mt][nt][1] + bv1);
            float2 v1 = make_float2(c[mt][nt][2] + bv0, c[mt][nt][3] + bv1);
            *(float2*)&out[r * DMODEL + col] = v0;
            *(float2*)&out[(r + 8) * DMODEL + col] = v1;
        }
    }
}

// ---------------------------------------------------------------------------
extern "C" void kernel_launch(void* const* d_in, const int* in_sizes, int n_in,
                              void* d_out, int out_size) {
    const float* query = (const float*)d_in[0];
    const float* key   = (const float*)d_in[1];
    const float* value = (const float*)d_in[2];
    const float* Wq    = (const float*)d_in[3];
    const float* bq    = (const float*)d_in[4];
    const float* Wk    = (const float*)d_in[5];
    const float* bk    = (const float*)d_in[6];
    const float* Wv    = (const float*)d_in[7];
    const float* bv    = (const float*)d_in[8];
    const float* Wo    = (const float*)d_in[9];
    const float* bo    = (const float*)d_in[10];
    float* out = (float*)d_out;

    const int ATTN_SMEM = (128 + 64 + 64) * 36 * (int)sizeof(uint32_t); // 36864
    const int OUTP_SMEM = (128 + 64) * AP * (int)sizeof(__half);        // 27648

    wosum_kernel<<<256, 256>>>(Wo);
    proj_kernel<<<dim3(128, 3), 256>>>(query, key, value,
                                       Wq, Wk, Wv, bq, bk, bv);
    attn_kernel<<<dim3(SS / 128, BB, NSPLIT), 256, ATTN_SMEM>>>();
    combine_kernel<<<MTOT / 8, 256>>>();
    outproj_kernel<<<dim3(MTOT / 128, DMODEL / 64), 256, OUTP_SMEM>>>(bo, out);
}

// round 14
// speedup vs baseline: 1.1084x; 1.0413x over previous
#include <cuda_runtime.h>
#include <cuda_fp16.h>
#include <cstdint>

// Problem dims
#define BB 8
#define SS 2048
#define DMODEL 1024
#define HDIM 64
#define NHEADS 16
#define MTOT (BB * SS)   // 16384 tokens
#define NSPLIT 4         // KV splits
#define KPS (SS / NSPLIT) // 512 keys per split

// ---------------------------------------------------------------------------
// Scratch (fp16 operands, fp32 partials).
// q,k,ctx: [token][64] row-major.  v: TRANSPOSED [b][dim][s].  wo: [n][d].
// ---------------------------------------------------------------------------
__device__ __half g_qh[MTOT * HDIM];
__device__ __half g_kh[MTOT * HDIM];
__device__ __half g_vh[MTOT * HDIM];     // [b][dim][s]
__device__ __half g_ch[MTOT * HDIM];
__device__ __half g_woh[DMODEL * HDIM];  // [n][d]
// Split-KV partials (fp32, unnormalized o; m,l in log2 domain)
__device__ float g_po[NSPLIT * MTOT * HDIM];
__device__ float g_pm[NSPLIT * MTOT];
__device__ float g_pl[NSPLIT * MTOT];

// ---------------------------------------------------------------------------
// Helpers
// ---------------------------------------------------------------------------
__device__ __forceinline__ void mma_fp16(float c[4],
                                         uint32_t a0, uint32_t a1, uint32_t a2, uint32_t a3,
                                         uint32_t b0, uint32_t b1) {
    asm volatile(
        "mma.sync.aligned.m16n8k16.row.col.f32.f16.f16.f32 "
        "{%0,%1,%2,%3}, {%4,%5,%6,%7}, {%8,%9}, {%0,%1,%2,%3};\n"
        : "+f"(c[0]), "+f"(c[1]), "+f"(c[2]), "+f"(c[3])
        : "r"(a0), "r"(a1), "r"(a2), "r"(a3), "r"(b0), "r"(b1));
}

__device__ __forceinline__ uint32_t pack2h(float x, float y) {
    __half2 h = __floats2half2_rn(x, y);
    return *reinterpret_cast<uint32_t*>(&h);
}

__device__ __forceinline__ void cp_async16(void* dst_smem, const void* src) {
    uint32_t d = (uint32_t)__cvta_generic_to_shared(dst_smem);
    asm volatile("cp.async.cg.shared.global [%0], [%1], 16;" :: "r"(d), "l"(src));
}
#define CP_COMMIT() asm volatile("cp.async.commit_group;")
#define CP_WAIT2()  asm volatile("cp.async.wait_group 2;")

// ---------------------------------------------------------------------------
// Kernel 1: Wo_sum^T[n][d] = sum_h Wo[h*64+d][n]  (fp16)
// ---------------------------------------------------------------------------
__global__ void wosum_kernel(const float* __restrict__ Wo) {
    int idx = blockIdx.x * blockDim.x + threadIdx.x;   // 0..65535
    int d = idx >> 10;
    int n = idx & (DMODEL - 1);
    float s = 0.f;
#pragma unroll
    for (int h = 0; h < NHEADS; h++)
        s += Wo[(h * HDIM + d) * DMODEL + n];
    g_woh[n * HDIM + d] = __float2half_rn(s);
}

// ---------------------------------------------------------------------------
// Kernel 2: fused q/k/v projections (fp16 MMA, fp32 accum).
// X[16384,1024] @ W[1024,64] + b.  BM=128, BN=64, BK=64. 256 thr, 8 warps.
// 3-stage cp.async pipeline: fp32 tiles stream global->smem asynchronously
// (144 KB in flight/block), converted to fp16 buffers per tile, then MMA.
// Each thread converts exactly the float4s it cp.async'd itself, so
// wait_group + block barriers are the only sync needed.
// q scaled by 0.125*log2(e) (softmax runs in base-2); v written [b][dim][s].
// ---------------------------------------------------------------------------
#define AP 72   // smem pitch (halves)
#define QSCALE (0.125f * 1.4426950408889634f)
#define A32STG (128 * 64)   // floats per A stage
#define B32STG (64 * 64)    // floats per B stage
#define PROJ_SMEM (3 * A32STG * 4 + 3 * B32STG * 4 + (128 + 64) * AP * 2)

__global__ __launch_bounds__(256) void proj_kernel(
    const float* __restrict__ Xq, const float* __restrict__ Xk, const float* __restrict__ Xv,
    const float* __restrict__ Wq, const float* __restrict__ Wk, const float* __restrict__ Wv,
    const float* __restrict__ bq, const float* __restrict__ bk, const float* __restrict__ bv) {

    const int which = blockIdx.y;
    const float* X;  const float* W;  const float* bias;
    if (which == 0)      { X = Xq; W = Wq; bias = bq; }
    else if (which == 1) { X = Xk; W = Wk; bias = bk; }
    else                 { X = Xv; W = Wv; bias = bv; }

    extern __shared__ char smraw[];
    float*  A32 = (float*)smraw;                                  // [3][128*64]
    float*  B32 = (float*)(smraw + 3 * A32STG * 4);               // [3][64*64]
    __half* Ash = (__half*)(smraw + 3 * A32STG * 4 + 3 * B32STG * 4); // [128][AP]
    __half* Bsh = Ash + 128 * AP;                                 // [64][AP] (W^T: [n][k])

    const int tid  = threadIdx.x;
    const int warp = tid >> 5, lane = tid & 31;
    const int g = lane >> 2, tig = lane & 3;
    const int wm = warp & 3, wn = warp >> 2;
    const int row0 = blockIdx.x * 128;

    float c[2][4][4];
#pragma unroll
    for (int mt = 0; mt < 2; mt++)
#pragma unroll
        for (int nt = 0; nt < 4; nt++)
#pragma unroll
            for (int j = 0; j < 4; j++) c[mt][nt][j] = 0.f;

    // Per-thread load slots (identical mapping for cp.async and convert)
    // A: 8 float4/thread; B: 4 float4/thread.
    // Prologue: issue stages for tiles 0,1,2.
#pragma unroll
    for (int t = 0; t < 3; t++) {
        float* a32 = A32 + t * A32STG;
        float* b32 = B32 + t * B32STG;
        const int k0 = t * 64;
#pragma unroll
        for (int it = 0; it < 8; it++) {
            int id = tid + it * 256;
            int r = id >> 4, cg = (id & 15) * 4;
            cp_async16(a32 + r * 64 + cg, X + (row0 + r) * DMODEL + k0 + cg);
        }
#pragma unroll
        for (int it = 0; it < 4; it++) {
            int id = tid + it * 256;
            int kr = id >> 4, cg = (id & 15) * 4;
            cp_async16(b32 + kr * 64 + cg, W + (k0 + kr) * HDIM + cg);
        }
        CP_COMMIT();
    }

    for (int t = 0; t < 16; t++) {
        CP_WAIT2();            // tile t's stage arrived (self-written data)
        __syncthreads();       // everyone past previous MMA before fp16 overwrite

        const int stg = t % 3;
        float* a32 = A32 + stg * A32STG;
        float* b32 = B32 + stg * B32STG;

        // Convert fp32 stage -> fp16 tile buffers
#pragma unroll
        for (int it = 0; it < 8; it++) {
            int id = tid + it * 256;
            int r = id >> 4, cg = (id & 15) * 4;
            float4 x4 = *(const float4*)(a32 + r * 64 + cg);
            uint2 p;
            p.x = pack2h(x4.x, x4.y);
            p.y = pack2h(x4.z, x4.w);
            *(uint2*)&Ash[r * AP + cg] = p;
        }
#pragma unroll
        for (int it = 0; it < 4; it++) {
            int id = tid + it * 256;
            int kr = id >> 4, cg = (id & 15) * 4;
            float4 w4 = *(const float4*)(b32 + kr * 64 + cg);
            Bsh[(cg + 0) * AP + kr] = __float2half_rn(w4.x);
            Bsh[(cg + 1) * AP + kr] = __float2half_rn(w4.y);
            Bsh[(cg + 2) * AP + kr] = __float2half_rn(w4.z);
            Bsh[(cg + 3) * AP + kr] = __float2half_rn(w4.w);
        }

        // Refill this stage with tile t+3 (thread-local slots; safe now)
        if (t + 3 < 16) {
            const int k0 = (t + 3) * 64;
#pragma unroll
            for (int it = 0; it < 8; it++) {
                int id = tid + it * 256;
                int r = id >> 4, cg = (id & 15) * 4;
                cp_async16(a32 + r * 64 + cg, X + (row0 + r) * DMODEL + k0 + cg);
            }
#pragma unroll
            for (int it = 0; it < 4; it++) {
                int id = tid + it * 256;
                int kr = id >> 4, cg = (id & 15) * 4;
                cp_async16(b32 + kr * 64 + cg, W + (k0 + kr) * HDIM + cg);
            }
        }
        CP_COMMIT();           // empty group in the tail keeps wait-count fixed
        __syncthreads();       // fp16 buffers complete

        // MMA over this 64-wide k-tile
#pragma unroll
        for (int kc = 0; kc < 4; kc++) {
            const int kb = kc * 16;
            uint32_t ah[2][4];
#pragma unroll
            for (int mt = 0; mt < 2; mt++) {
                int r = wm * 32 + mt * 16 + g;
                ah[mt][0] = *(const uint32_t*)&Ash[r * AP + kb + 2 * tig];
                ah[mt][1] = *(const uint32_t*)&Ash[(r + 8) * AP + kb + 2 * tig];
                ah[mt][2] = *(const uint32_t*)&Ash[r * AP + kb + 8 + 2 * tig];
                ah[mt][3] = *(const uint32_t*)&Ash[(r + 8) * AP + kb + 8 + 2 * tig];
            }
#pragma unroll
            for (int nt = 0; nt < 4; nt++) {
                int n = wn * 32 + nt * 8 + g;
                uint32_t bh0 = *(const uint32_t*)&Bsh[n * AP + kb + 2 * tig];
                uint32_t bh1 = *(const uint32_t*)&Bsh[n * AP + kb + 8 + 2 * tig];
#pragma unroll
                for (int mt = 0; mt < 2; mt++)
                    mma_fp16(c[mt][nt], ah[mt][0], ah[mt][1], ah[mt][2], ah[mt][3], bh0, bh1);
            }
        }
    }

    const float scale = (which == 0) ? QSCALE : 1.0f;
    __half* oh = (which == 0) ? g_qh : g_kh;

#pragma unroll
    for (int mt = 0; mt < 2; mt++) {
#pragma unroll
        for (int nt = 0; nt < 4; nt++) {
            int r   = row0 + wm * 32 + mt * 16 + g;
            int col = wn * 32 + nt * 8 + 2 * tig;
            float bv0 = bias[col], bv1 = bias[col + 1];
            float v0 = (c[mt][nt][0] + bv0) * scale;
            float v1 = (c[mt][nt][1] + bv1) * scale;
            float v2 = (c[mt][nt][2] + bv0) * scale;   // row r+8
            float v3 = (c[mt][nt][3] + bv1) * scale;
            if (which < 2) {
                *(uint32_t*)&oh[r * HDIM + col]       = pack2h(v0, v1);
                *(uint32_t*)&oh[(r + 8) * HDIM + col] = pack2h(v2, v3);
            } else {
                // v transposed: [b][dim][s]
                int b = r >> 11, s = r & 2047;
                g_vh[(b * HDIM + col) * SS + s]         = __float2half_rn(v0);
                g_vh[(b * HDIM + col + 1) * SS + s]     = __float2half_rn(v1);
                g_vh[(b * HDIM + col) * SS + s + 8]     = __float2half_rn(v2);
                g_vh[(b * HDIM + col + 1) * SS + s + 8] = __float2half_rn(v3);
            }
        }
    }
}

// ---------------------------------------------------------------------------
// Kernel 3: split-KV flash attention (fp16 tensor cores).
// grid (S/128, B, NSPLIT); block 256 (8 warps, warp owns 16 q-rows).
// (Identical to the 154.0us round-13 version.)
// ---------------------------------------------------------------------------
__global__ __launch_bounds__(256, 2) void attn_kernel() {
    extern __shared__ uint32_t sm32[];
    uint32_t* Qs = sm32;                 // [128][36]
    uint32_t* Ks = sm32 + 128 * 36;      // [64][36]
    uint32_t* Vs = sm32 + (128 + 64) * 36; // [64][36]

    const int tid = threadIdx.x, warp = tid >> 5, lane = tid & 31;
    const int g = lane >> 2, tig = lane & 3;
    const int bq = blockIdx.x, b = blockIdx.y, split = blockIdx.z;
    const int t0 = b * SS + bq * 128;
    const int kt0 = split * (KPS / 64);

    const uint32_t* qb32 = (const uint32_t*)g_qh;
    const uint32_t* kb32 = (const uint32_t*)(g_kh + (size_t)b * SS * HDIM);
    const uint32_t* vb32 = (const uint32_t*)(g_vh + (size_t)b * HDIM * SS);

    // Stage Q tile (128 rows x 32 u32)
#pragma unroll
    for (int it = 0; it < 16; it++) {
        int id = tid + it * 256;
        int r = id >> 5, dp = id & 31;
        Qs[r * 36 + dp] = qb32[(t0 + r) * 32 + dp];
    }
    __syncthreads();

    // Hoist Q fragments (loop-invariant across kt): 16 u32 regs
    const int qr = warp * 16 + g;
    uint32_t qf[4][4];
#pragma unroll
    for (int kc = 0; kc < 4; kc++) {
        qf[kc][0] = Qs[qr * 36 + kc * 8 + tig];
        qf[kc][1] = Qs[(qr + 8) * 36 + kc * 8 + tig];
        qf[kc][2] = Qs[qr * 36 + kc * 8 + 4 + tig];
        qf[kc][3] = Qs[(qr + 8) * 36 + kc * 8 + 4 + tig];
    }

    float m0 = -1e30f, m1 = -1e30f, l0 = 0.f, l1 = 0.f;   // l: per-lane partial
    float o[8][4];
#pragma unroll
    for (int nt = 0; nt < 8; nt++)
#pragma unroll
        for (int j = 0; j < 4; j++) o[nt][j] = 0.f;

    for (int kt = kt0; kt < kt0 + KPS / 64; kt++) {
        // Stage K and V tiles (64 rows x 32 u32 each), 8 u32 per thread each
#pragma unroll
        for (int it = 0; it < 8; it++) {
            int id = tid + it * 256;
            int r = id >> 5, dp = id & 31;
            Ks[r * 36 + dp] = kb32[(kt * 64 + r) * 32 + dp];
            Vs[r * 36 + dp] = vb32[r * 1024 + kt * 32 + dp];
        }
        __syncthreads();

        // S = Q K^T
        float s[8][4];
#pragma unroll
        for (int nt = 0; nt < 8; nt++)
#pragma unroll
            for (int j = 0; j < 4; j++) s[nt][j] = 0.f;

#pragma unroll
        for (int kc = 0; kc < 4; kc++) {
#pragma unroll
            for (int nt = 0; nt < 8; nt++) {
                int n = nt * 8 + g;
                uint32_t kf0 = Ks[n * 36 + kc * 8 + tig];
                uint32_t kf1 = Ks[n * 36 + kc * 8 + 4 + tig];
                mma_fp16(s[nt], qf[kc][0], qf[kc][1], qf[kc][2], qf[kc][3], kf0, kf1);
            }
        }

        // Online softmax, base-2 domain. Max reduced across tig; l deferred.
        float mt0 = -1e30f, mt1 = -1e30f;
#pragma unroll
        for (int nt = 0; nt < 8; nt++) {
            mt0 = fmaxf(mt0, fmaxf(s[nt][0], s[nt][1]));
            mt1 = fmaxf(mt1, fmaxf(s[nt][2], s[nt][3]));
        }
        mt0 = fmaxf(mt0, __shfl_xor_sync(0xffffffffu, mt0, 1));
        mt0 = fmaxf(mt0, __shfl_xor_sync(0xffffffffu, mt0, 2));
        mt1 = fmaxf(mt1, __shfl_xor_sync(0xffffffffu, mt1, 1));
        mt1 = fmaxf(mt1, __shfl_xor_sync(0xffffffffu, mt1, 2));
        float mn0 = fmaxf(m0, mt0), mn1 = fmaxf(m1, mt1);
        float cr0 = exp2f(m0 - mn0), cr1 = exp2f(m1 - mn1);
        m0 = mn0; m1 = mn1;
        float ls0 = 0.f, ls1 = 0.f;
#pragma unroll
        for (int nt = 0; nt < 8; nt++) {
            s[nt][0] = exp2f(s[nt][0] - mn0); ls0 += s[nt][0];
            s[nt][1] = exp2f(s[nt][1] - mn0); ls0 += s[nt][1];
            s[nt][2] = exp2f(s[nt][2] - mn1); ls1 += s[nt][2];
            s[nt][3] = exp2f(s[nt][3] - mn1); ls1 += s[nt][3];
        }
        l0 = l0 * cr0 + ls0;      // per-lane partial (cr uniform across tig)
        l1 = l1 * cr1 + ls1;
#pragma unroll
        for (int nt = 0; nt < 8; nt++) {
            o[nt][0] *= cr0; o[nt][1] *= cr0;
            o[nt][2] *= cr1; o[nt][3] *= cr1;
        }

        // ctx += P V  (P fragments straight from accumulators)
#pragma unroll
        for (int kc = 0; kc < 4; kc++) {
            uint32_t ph0 = pack2h(s[2 * kc][0],     s[2 * kc][1]);
            uint32_t ph1 = pack2h(s[2 * kc][2],     s[2 * kc][3]);
            uint32_t ph2 = pack2h(s[2 * kc + 1][0], s[2 * kc + 1][1]);
            uint32_t ph3 = pack2h(s[2 * kc + 1][2], s[2 * kc + 1][3]);
#pragma unroll
            for (int nt = 0; nt < 8; nt++) {
                int n = nt * 8 + g;
                uint32_t vf0 = Vs[n * 36 + kc * 8 + tig];
                uint32_t vf1 = Vs[n * 36 + kc * 8 + 4 + tig];
                mma_fp16(o[nt], ph0, ph1, ph2, ph3, vf0, vf1);
            }
        }
        __syncthreads();
    }

    // Final l reduction across the 4 tig lanes
    l0 += __shfl_xor_sync(0xffffffffu, l0, 1);
    l0 += __shfl_xor_sync(0xffffffffu, l0, 2);
    l1 += __shfl_xor_sync(0xffffffffu, l1, 1);
    l1 += __shfl_xor_sync(0xffffffffu, l1, 2);

    // Write unnormalized partials
    const int r = t0 + warp * 16 + g;
    float* po = g_po + (size_t)split * MTOT * HDIM;
#pragma unroll
    for (int nt = 0; nt < 8; nt++) {
        int col = nt * 8 + 2 * tig;
        *(float2*)&po[r * HDIM + col]       = make_float2(o[nt][0], o[nt][1]);
        *(float2*)&po[(r + 8) * HDIM + col] = make_float2(o[nt][2], o[nt][3]);
    }
    if (tig == 0) {
        g_pm[split * MTOT + r]     = m0;
        g_pm[split * MTOT + r + 8] = m1;
        g_pl[split * MTOT + r]     = l0;
        g_pl[split * MTOT + r + 8] = l1;
    }
}

// ---------------------------------------------------------------------------
// Kernel 3b: combine split-KV partials -> ctx (fp16).
// ---------------------------------------------------------------------------
__global__ __launch_bounds__(256) void combine_kernel() {
    const int warp = threadIdx.x >> 5, lane = threadIdx.x & 31;
    const int row = blockIdx.x * 8 + warp;
    const int col = lane * 2;

    float m[NSPLIT], lpart[NSPLIT];
    float M = -1e30f;
#pragma unroll
    for (int i = 0; i < NSPLIT; i++) {
        m[i] = g_pm[i * MTOT + row];
        lpart[i] = g_pl[i * MTOT + row];
        M = fmaxf(M, m[i]);
    }
    float L = 0.f, w[NSPLIT];
#pragma unroll
    for (int i = 0; i < NSPLIT; i++) {
        w[i] = exp2f(m[i] - M);
        L += w[i] * lpart[i];
    }
    float inv = 1.0f / L;
    float c0 = 0.f, c1 = 0.f;
#pragma unroll
    for (int i = 0; i < NSPLIT; i++) {
        float2 ov = *(const float2*)&g_po[((size_t)i * MTOT + row) * HDIM + col];
        c0 += w[i] * ov.x;
        c1 += w[i] * ov.y;
    }
    *(uint32_t*)&g_ch[row * HDIM + col] = pack2h(c0 * inv, c1 * inv);
}

// ---------------------------------------------------------------------------
// Kernel 4: out = ctx[16384,64] @ Wo_sum[64,1024] + bo (fp16 MMA).
// BM=128, BN=64, K=64.  (Identical to the round-5/10/13 version.)
// ---------------------------------------------------------------------------
__global__ __launch_bounds__(256) void outproj_kernel(const float* __restrict__ bo,
                                                      float* __restrict__ out) {
    extern __shared__ __half smh[];
    __half* Ash = smh;              // ctx [128][AP]
    __half* Bsh = smh + 128 * AP;   // woT [64][AP]

    const int tid = threadIdx.x, warp = tid >> 5, lane = tid & 31;
    const int g = lane >> 2, tig = lane & 3;
    const int wm = warp & 3, wn = warp >> 2;
    const int row0 = blockIdx.x * 128, n0 = blockIdx.y * 64;

#pragma unroll
    for (int it = 0; it < 16; it++) {
        int id = tid + it * 256;                  // 0..4095 u32s
        int r = id >> 5, dp = (id & 31) * 2;
        *(uint32_t*)&Ash[r * AP + dp] = *(const uint32_t*)&g_ch[(row0 + r) * HDIM + dp];
    }
#pragma unroll
    for (int it = 0; it < 8; it++) {
        int id = tid + it * 256;                  // 0..2047 u32s
        int n = id >> 5, dp = (id & 31) * 2;
        *(uint32_t*)&Bsh[n * AP + dp] = *(const uint32_t*)&g_woh[(n0 + n) * HDIM + dp];
    }
    __syncthreads();

    float c[2][4][4];
#pragma unroll
    for (int mt = 0; mt < 2; mt++)
#pragma unroll
        for (int nt = 0; nt < 4; nt++)
#pragma unroll
            for (int j = 0; j < 4; j++) c[mt][nt][j] = 0.f;

#pragma unroll
    for (int kc = 0; kc < 4; kc++) {
        const int kb = kc * 16;
        uint32_t ah[2][4];
#pragma unroll
        for (int mt = 0; mt < 2; mt++) {
            int r = wm * 32 + mt * 16 + g;
            ah[mt][0] = *(const uint32_t*)&Ash[r * AP + kb + 2 * tig];
            ah[mt][1] = *(const uint32_t*)&Ash[(r + 8) * AP + kb + 2 * tig];
            ah[mt][2] = *(const uint32_t*)&Ash[r * AP + kb + 8 + 2 * tig];
            ah[mt][3] = *(const uint32_t*)&Ash[(r + 8) * AP + kb + 8 + 2 * tig];
        }
#pragma unroll
        for (int nt = 0; nt < 4; nt++) {
            int n = wn * 32 + nt * 8 + g;
            uint32_t bh0 = *(const uint32_t*)&Bsh[n * AP + kb + 2 * tig];
            uint32_t bh1 = *(const uint32_t*)&Bsh[n * AP + kb + 8 + 2 * tig];
#pragma unroll
            for (int mt = 0; mt < 2; mt++)
                mma_fp16(c[mt][nt], ah[mt][0], ah[mt][1], ah[mt][2], ah[mt][3], bh0, bh1);
        }
    }

#pragma unroll
    for (int mt = 0; mt < 2; mt++) {
#pragma unroll
        for (int nt = 0; nt < 4; nt++) {
            int r   = row0 + wm * 32 + mt * 16 + g;
            int col = n0 + wn * 32 + nt * 8 + 2 * tig;
            float bv0 = bo[col], bv1 = bo[col + 1];
            float2 v0 = make_float2(c[mt][nt][0] + bv0, c[mt][nt][1] + bv1);
            float2 v1 = make_float2(c[mt][nt][2] + bv0, c[mt][nt][3] + bv1);
            *(float2*)&out[r * DMODEL + col] = v0;
            *(float2*)&out[(r + 8) * DMODEL + col] = v1;
        }
    }
}

// ---------------------------------------------------------------------------
extern "C" void kernel_launch(void* const* d_in, const int* in_sizes, int n_in,
                              void* d_out, int out_size) {
    const float* query = (const float*)d_in[0];
    const float* key   = (const float*)d_in[1];
    const float* value = (const float*)d_in[2];
    const float* Wq    = (const float*)d_in[3];
    const float* bq    = (const float*)d_in[4];
    const float* Wk    = (const float*)d_in[5];
    const float* bk    = (const float*)d_in[6];
    const float* Wv    = (const float*)d_in[7];
    const float* bv    = (const float*)d_in[8];
    const float* Wo    = (const float*)d_in[9];
    const float* bo    = (const float*)d_in[10];
    float* out = (float*)d_out;

    const int ATTN_SMEM = (128 + 64 + 64) * 36 * (int)sizeof(uint32_t); // 36864
    const int OUTP_SMEM = (128 + 64) * AP * (int)sizeof(__half);        // 27648

    // proj needs 171 KB dynamic smem (idempotent attribute set, every launch)
    cudaFuncSetAttribute(proj_kernel,
                         cudaFuncAttributeMaxDynamicSharedMemorySize, PROJ_SMEM);

    wosum_kernel<<<256, 256>>>(Wo);
    proj_kernel<<<dim3(128, 3), 256, PROJ_SMEM>>>(query, key, value,
                                                  Wq, Wk, Wv, bq, bk, bv);
    attn_kernel<<<dim3(SS / 128, BB, NSPLIT), 256, ATTN_SMEM>>>();
    combine_kernel<<<MTOT / 8, 256>>>();
    outproj_kernel<<<dim3(MTOT / 128, DMODEL / 64), 256, OUTP_SMEM>>>(bo, out);
}

// round 17
// speedup vs baseline: 1.1242x; 1.0143x over previous
#include <cuda_runtime.h>
#include <cuda_fp16.h>
#include <cstdint>

// Problem dims
#define BB 8
#define SS 2048
#define DMODEL 1024
#define HDIM 64
#define NHEADS 16
#define MTOT (BB * SS)   // 16384 tokens
#define NSPLIT 2         // KV splits
#define KPS (SS / NSPLIT) // 1024 keys per split

// ---------------------------------------------------------------------------
// Scratch (fp16 operands, fp32 partials).
// q,k,ctx: [token][64] row-major.  v: TRANSPOSED [b][dim][s].  wo: [n][d].
// ---------------------------------------------------------------------------
__device__ __half g_qh[MTOT * HDIM];
__device__ __half g_kh[MTOT * HDIM];
__device__ __half g_vh[MTOT * HDIM];     // [b][dim][s]
__device__ __half g_ch[MTOT * HDIM];
__device__ __half g_woh[DMODEL * HDIM];  // [n][d]
// Split-KV partials (fp32, unnormalized o; m,l in log2 domain)
__device__ float g_po[NSPLIT * MTOT * HDIM];
__device__ float g_pm[NSPLIT * MTOT];
__device__ float g_pl[NSPLIT * MTOT];

// ---------------------------------------------------------------------------
// Helpers
// ---------------------------------------------------------------------------
__device__ __forceinline__ void mma_fp16(float c[4],
                                         uint32_t a0, uint32_t a1, uint32_t a2, uint32_t a3,
                                         uint32_t b0, uint32_t b1) {
    asm volatile(
        "mma.sync.aligned.m16n8k16.row.col.f32.f16.f16.f32 "
        "{%0,%1,%2,%3}, {%4,%5,%6,%7}, {%8,%9}, {%0,%1,%2,%3};\n"
        : "+f"(c[0]), "+f"(c[1]), "+f"(c[2]), "+f"(c[3])
        : "r"(a0), "r"(a1), "r"(a2), "r"(a3), "r"(b0), "r"(b1));
}

__device__ __forceinline__ uint32_t pack2h(float x, float y) {
    __half2 h = __floats2half2_rn(x, y);
    return *reinterpret_cast<uint32_t*>(&h);
}

__device__ __forceinline__ void cp_async16(void* dst_smem, const void* src) {
    uint32_t d = (uint32_t)__cvta_generic_to_shared(dst_smem);
    asm volatile("cp.async.cg.shared.global [%0], [%1], 16;" :: "r"(d), "l"(src));
}
#define CP_COMMIT() asm volatile("cp.async.commit_group;")
#define CP_WAIT2()  asm volatile("cp.async.wait_group 2;")

// ---------------------------------------------------------------------------
// Kernel 1: Wo_sum^T[n][d] = sum_h Wo[h*64+d][n]  (fp16)
// ---------------------------------------------------------------------------
__global__ void wosum_kernel(const float* __restrict__ Wo) {
    int idx = blockIdx.x * blockDim.x + threadIdx.x;   // 0..65535
    int d = idx >> 10;
    int n = idx & (DMODEL - 1);
    float s = 0.f;
#pragma unroll
    for (int h = 0; h < NHEADS; h++)
        s += Wo[(h * HDIM + d) * DMODEL + n];
    g_woh[n * HDIM + d] = __float2half_rn(s);
}

// ---------------------------------------------------------------------------
// Kernel 2: fused q/k/v projections (fp16 MMA, fp32 accum).
// X[16384,1024] @ W[1024,64] + b.  BM=128, BN=64, BK=32. 256 thr, 8 warps.
// 3-stage cp.async pipeline with SMALL stages (A 16 KB, B 8 KB fp32):
// total smem 87 KB -> 2 blocks/SM (vs 1 before). 384 blocks now run in
// ~1.3 waves instead of 2.6, and barriers interleave across blocks.
// Fragment layout: round-5-proven pitch-40.
// q scaled by 0.125*log2(e); v written [b][dim][s].
// ---------------------------------------------------------------------------
#define PP 40   // fp16 smem pitch (halves) for BK=32 tiles
#define QSCALE (0.125f * 1.4426950408889634f)
#define A32STG (128 * 32)   // floats per A stage (16 KB)
#define B32STG (32 * 64)    // floats per B stage (8 KB)
#define PROJ_SMEM (3 * (A32STG + B32STG) * 4 + (128 + 64) * PP * 2)  // 89088 B

__global__ __launch_bounds__(256) void proj_kernel(
    const float* __restrict__ Xq, const float* __restrict__ Xk, const float* __restrict__ Xv,
    const float* __restrict__ Wq, const float* __restrict__ Wk, const float* __restrict__ Wv,
    const float* __restrict__ bq, const float* __restrict__ bk, const float* __restrict__ bv) {

    const int which = blockIdx.y;
    const float* X;  const float* W;  const float* bias;
    if (which == 0)      { X = Xq; W = Wq; bias = bq; }
    else if (which == 1) { X = Xk; W = Wk; bias = bk; }
    else                 { X = Xv; W = Wv; bias = bv; }

    extern __shared__ char smraw[];
    float*  A32 = (float*)smraw;                                   // [3][128*32]
    float*  B32 = (float*)(smraw + 3 * A32STG * 4);                // [3][32*64]
    __half* Ash = (__half*)(smraw + 3 * (A32STG + B32STG) * 4);    // [128][PP]
    __half* Bsh = Ash + 128 * PP;                                  // [64][PP] (W^T: [n][k])

    const int tid  = threadIdx.x;
    const int warp = tid >> 5, lane = tid & 31;
    const int g = lane >> 2, tig = lane & 3;
    const int wm = warp & 3, wn = warp >> 2;
    const int row0 = blockIdx.x * 128;

    float c[2][4][4];
#pragma unroll
    for (int mt = 0; mt < 2; mt++)
#pragma unroll
        for (int nt = 0; nt < 4; nt++)
#pragma unroll
            for (int j = 0; j < 4; j++) c[mt][nt][j] = 0.f;

    // Per-thread slots: A 4 float4/thread, B 2 float4/thread.
    // Prologue: issue stages for tiles 0,1,2.
#pragma unroll
    for (int t = 0; t < 3; t++) {
        float* a32 = A32 + t * A32STG;
        float* b32 = B32 + t * B32STG;
        const int k0 = t * 32;
#pragma unroll
        for (int it = 0; it < 4; it++) {
            int id = tid + it * 256;             // 0..1023 float4s
            int r = id >> 3, cg = (id & 7) * 4;
            cp_async16(a32 + r * 32 + cg, X + (row0 + r) * DMODEL + k0 + cg);
        }
#pragma unroll
        for (int it = 0; it < 2; it++) {
            int id = tid + it * 256;             // 0..511 float4s
            int kr = id >> 4, cg = (id & 15) * 4;
            cp_async16(b32 + kr * 64 + cg, W + (k0 + kr) * HDIM + cg);
        }
        CP_COMMIT();
    }

    for (int t = 0; t < 32; t++) {
        CP_WAIT2();            // tile t's stage arrived
        __syncthreads();       // previous MMA done before fp16 overwrite

        const int stg = t % 3;
        float* a32 = A32 + stg * A32STG;
        float* b32 = B32 + stg * B32STG;

        // Convert fp32 stage -> fp16 tile buffers (thread-local slots)
#pragma unroll
        for (int it = 0; it < 4; it++) {
            int id = tid + it * 256;
            int r = id >> 3, cg = (id & 7) * 4;
            float4 x4 = *(const float4*)(a32 + r * 32 + cg);
            uint2 p;
            p.x = pack2h(x4.x, x4.y);
            p.y = pack2h(x4.z, x4.w);
            *(uint2*)&Ash[r * PP + cg] = p;
        }
#pragma unroll
        for (int it = 0; it < 2; it++) {
            int id = tid + it * 256;
            int kr = id >> 4, cg = (id & 15) * 4;
            float4 w4 = *(const float4*)(b32 + kr * 64 + cg);
            Bsh[(cg + 0) * PP + kr] = __float2half_rn(w4.x);
            Bsh[(cg + 1) * PP + kr] = __float2half_rn(w4.y);
            Bsh[(cg + 2) * PP + kr] = __float2half_rn(w4.z);
            Bsh[(cg + 3) * PP + kr] = __float2half_rn(w4.w);
        }

        // Refill this stage with tile t+3
        if (t + 3 < 32) {
            const int k0 = (t + 3) * 32;
#pragma unroll
            for (int it = 0; it < 4; it++) {
                int id = tid + it * 256;
                int r = id >> 3, cg = (id & 7) * 4;
                cp_async16(a32 + r * 32 + cg, X + (row0 + r) * DMODEL + k0 + cg);
            }
#pragma unroll
            for (int it = 0; it < 2; it++) {
                int id = tid + it * 256;
                int kr = id >> 4, cg = (id & 15) * 4;
                cp_async16(b32 + kr * 64 + cg, W + (k0 + kr) * HDIM + cg);
            }
        }
        CP_COMMIT();           // empty group in the tail keeps wait-count fixed
        __syncthreads();       // fp16 buffers complete

        // MMA over this 32-wide k-tile
#pragma unroll
        for (int kk = 0; kk < 2; kk++) {
            const int kb = kk * 16;
            uint32_t ah[2][4];
#pragma unroll
            for (int mt = 0; mt < 2; mt++) {
                int r = wm * 32 + mt * 16 + g;
                ah[mt][0] = *(const uint32_t*)&Ash[r * PP + kb + 2 * tig];
                ah[mt][1] = *(const uint32_t*)&Ash[(r + 8) * PP + kb + 2 * tig];
                ah[mt][2] = *(const uint32_t*)&Ash[r * PP + kb + 8 + 2 * tig];
                ah[mt][3] = *(const uint32_t*)&Ash[(r + 8) * PP + kb + 8 + 2 * tig];
            }
#pragma unroll
            for (int nt = 0; nt < 4; nt++) {
                int n = wn * 32 + nt * 8 + g;
                uint32_t bh0 = *(const uint32_t*)&Bsh[n * PP + kb + 2 * tig];
                uint32_t bh1 = *(const uint32_t*)&Bsh[n * PP + kb + 8 + 2 * tig];
#pragma unroll
                for (int mt = 0; mt < 2; mt++)
                    mma_fp16(c[mt][nt], ah[mt][0], ah[mt][1], ah[mt][2], ah[mt][3], bh0, bh1);
            }
        }
    }

    const float scale = (which == 0) ? QSCALE : 1.0f;
    __half* oh = (which == 0) ? g_qh : g_kh;

#pragma unroll
    for (int mt = 0; mt < 2; mt++) {
#pragma unroll
        for (int nt = 0; nt < 4; nt++) {
            int r   = row0 + wm * 32 + mt * 16 + g;
            int col = wn * 32 + nt * 8 + 2 * tig;
            float bv0 = bias[col], bv1 = bias[col + 1];
            float v0 = (c[mt][nt][0] + bv0) * scale;
            float v1 = (c[mt][nt][1] + bv1) * scale;
            float v2 = (c[mt][nt][2] + bv0) * scale;   // row r+8
            float v3 = (c[mt][nt][3] + bv1) * scale;
            if (which < 2) {
                *(uint32_t*)&oh[r * HDIM + col]       = pack2h(v0, v1);
                *(uint32_t*)&oh[(r + 8) * HDIM + col] = pack2h(v2, v3);
            } else {
                // v transposed: [b][dim][s]
                int b = r >> 11, s = r & 2047;
                g_vh[(b * HDIM + col) * SS + s]         = __float2half_rn(v0);
                g_vh[(b * HDIM + col + 1) * SS + s]     = __float2half_rn(v1);
                g_vh[(b * HDIM + col) * SS + s + 8]     = __float2half_rn(v2);
                g_vh[(b * HDIM + col + 1) * SS + s + 8] = __float2half_rn(v3);
            }
        }
    }
}

// ---------------------------------------------------------------------------
// Kernel 3: split-KV flash attention (fp16 tensor cores).
// grid (S/128, B, NSPLIT=2) = 256 blocks -> exactly one wave at 2 blocks/SM.
// block 256 (8 warps, warp owns 16 q-rows); inner loop identical to the
// proven round-13 version (16 k-tiles per block now).
// ---------------------------------------------------------------------------
__global__ __launch_bounds__(256, 2) void attn_kernel() {
    extern __shared__ uint32_t sm32[];
    uint32_t* Qs = sm32;                 // [128][36]
    uint32_t* Ks = sm32 + 128 * 36;      // [64][36]
    uint32_t* Vs = sm32 + (128 + 64) * 36; // [64][36]

    const int tid = threadIdx.x, warp = tid >> 5, lane = tid & 31;
    const int g = lane >> 2, tig = lane & 3;
    const int bq = blockIdx.x, b = blockIdx.y, split = blockIdx.z;
    const int t0 = b * SS + bq * 128;
    const int kt0 = split * (KPS / 64);

    const uint32_t* qb32 = (const uint32_t*)g_qh;
    const uint32_t* kb32 = (const uint32_t*)(g_kh + (size_t)b * SS * HDIM);
    const uint32_t* vb32 = (const uint32_t*)(g_vh + (size_t)b * HDIM * SS);

    // Stage Q tile (128 rows x 32 u32)
#pragma unroll
    for (int it = 0; it < 16; it++) {
        int id = tid + it * 256;
        int r = id >> 5, dp = id & 31;
        Qs[r * 36 + dp] = qb32[(t0 + r) * 32 + dp];
    }
    __syncthreads();

    // Hoist Q fragments (loop-invariant across kt): 16 u32 regs
    const int qr = warp * 16 + g;
    uint32_t qf[4][4];
#pragma unroll
    for (int kc = 0; kc < 4; kc++) {
        qf[kc][0] = Qs[qr * 36 + kc * 8 + tig];
        qf[kc][1] = Qs[(qr + 8) * 36 + kc * 8 + tig];
        qf[kc][2] = Qs[qr * 36 + kc * 8 + 4 + tig];
        qf[kc][3] = Qs[(qr + 8) * 36 + kc * 8 + 4 + tig];
    }

    float m0 = -1e30f, m1 = -1e30f, l0 = 0.f, l1 = 0.f;   // l: per-lane partial
    float o[8][4];
#pragma unroll
    for (int nt = 0; nt < 8; nt++)
#pragma unroll
        for (int j = 0; j < 4; j++) o[nt][j] = 0.f;

    for (int kt = kt0; kt < kt0 + KPS / 64; kt++) {
        // Stage K and V tiles (64 rows x 32 u32 each), 8 u32 per thread each
#pragma unroll
        for (int it = 0; it < 8; it++) {
            int id = tid + it * 256;
            int r = id >> 5, dp = id & 31;
            Ks[r * 36 + dp] = kb32[(kt * 64 + r) * 32 + dp];
            Vs[r * 36 + dp] = vb32[r * 1024 + kt * 32 + dp];
        }
        __syncthreads();

        // S = Q K^T
        float s[8][4];
#pragma unroll
        for (int nt = 0; nt < 8; nt++)
#pragma unroll
            for (int j = 0; j < 4; j++) s[nt][j] = 0.f;

#pragma unroll
        for (int kc = 0; kc < 4; kc++) {
#pragma unroll
            for (int nt = 0; nt < 8; nt++) {
                int n = nt * 8 + g;
                uint32_t kf0 = Ks[n * 36 + kc * 8 + tig];
                uint32_t kf1 = Ks[n * 36 + kc * 8 + 4 + tig];
                mma_fp16(s[nt], qf[kc][0], qf[kc][1], qf[kc][2], qf[kc][3], kf0, kf1);
            }
        }

        // Online softmax, base-2 domain. Max reduced across tig; l deferred.
        float mt0 = -1e30f, mt1 = -1e30f;
#pragma unroll
        for (int nt = 0; nt < 8; nt++) {
            mt0 = fmaxf(mt0, fmaxf(s[nt][0], s[nt][1]));
            mt1 = fmaxf(mt1, fmaxf(s[nt][2], s[nt][3]));
        }
        mt0 = fmaxf(mt0, __shfl_xor_sync(0xffffffffu, mt0, 1));
        mt0 = fmaxf(mt0, __shfl_xor_sync(0xffffffffu, mt0, 2));
        mt1 = fmaxf(mt1, __shfl_xor_sync(0xffffffffu, mt1, 1));
        mt1 = fmaxf(mt1, __shfl_xor_sync(0xffffffffu, mt1, 2));
        float mn0 = fmaxf(m0, mt0), mn1 = fmaxf(m1, mt1);
        float cr0 = exp2f(m0 - mn0), cr1 = exp2f(m1 - mn1);
        m0 = mn0; m1 = mn1;
        float ls0 = 0.f, ls1 = 0.f;
#pragma unroll
        for (int nt = 0; nt < 8; nt++) {
            s[nt][0] = exp2f(s[nt][0] - mn0); ls0 += s[nt][0];
            s[nt][1] = exp2f(s[nt][1] - mn0); ls0 += s[nt][1];
            s[nt][2] = exp2f(s[nt][2] - mn1); ls1 += s[nt][2];
            s[nt][3] = exp2f(s[nt][3] - mn1); ls1 += s[nt][3];
        }
        l0 = l0 * cr0 + ls0;      // per-lane partial (cr uniform across tig)
        l1 = l1 * cr1 + ls1;
#pragma unroll
        for (int nt = 0; nt < 8; nt++) {
            o[nt][0] *= cr0; o[nt][1] *= cr0;
            o[nt][2] *= cr1; o[nt][3] *= cr1;
        }

        // ctx += P V  (P fragments straight from accumulators)
#pragma unroll
        for (int kc = 0; kc < 4; kc++) {
            uint32_t ph0 = pack2h(s[2 * kc][0],     s[2 * kc][1]);
            uint32_t ph1 = pack2h(s[2 * kc][2],     s[2 * kc][3]);
            uint32_t ph2 = pack2h(s[2 * kc + 1][0], s[2 * kc + 1][1]);
            uint32_t ph3 = pack2h(s[2 * kc + 1][2], s[2 * kc + 1][3]);
#pragma unroll
            for (int nt = 0; nt < 8; nt++) {
                int n = nt * 8 + g;
                uint32_t vf0 = Vs[n * 36 + kc * 8 + tig];
                uint32_t vf1 = Vs[n * 36 + kc * 8 + 4 + tig];
                mma_fp16(o[nt], ph0, ph1, ph2, ph3, vf0, vf1);
            }
        }
        __syncthreads();
    }

    // Final l reduction across the 4 tig lanes
    l0 += __shfl_xor_sync(0xffffffffu, l0, 1);
    l0 += __shfl_xor_sync(0xffffffffu, l0, 2);
    l1 += __shfl_xor_sync(0xffffffffu, l1, 1);
    l1 += __shfl_xor_sync(0xffffffffu, l1, 2);

    // Write unnormalized partials
    const int r = t0 + warp * 16 + g;
    float* po = g_po + (size_t)split * MTOT * HDIM;
#pragma unroll
    for (int nt = 0; nt < 8; nt++) {
        int col = nt * 8 + 2 * tig;
        *(float2*)&po[r * HDIM + col]       = make_float2(o[nt][0], o[nt][1]);
        *(float2*)&po[(r + 8) * HDIM + col] = make_float2(o[nt][2], o[nt][3]);
    }
    if (tig == 0) {
        g_pm[split * MTOT + r]     = m0;
        g_pm[split * MTOT + r + 8] = m1;
        g_pl[split * MTOT + r]     = l0;
        g_pl[split * MTOT + r + 8] = l1;
    }
}

// ---------------------------------------------------------------------------
// Kernel 3b: combine split-KV partials -> ctx (fp16).
// ---------------------------------------------------------------------------
__global__ __launch_bounds__(256) void combine_kernel() {
    const int warp = threadIdx.x >> 5, lane = threadIdx.x & 31;
    const int row = blockIdx.x * 8 + warp;
    const int col = lane * 2;

    float m[NSPLIT], lpart[NSPLIT];
    float M = -1e30f;
#pragma unroll
    for (int i = 0; i < NSPLIT; i++) {
        m[i] = g_pm[i * MTOT + row];
        lpart[i] = g_pl[i * MTOT + row];
        M = fmaxf(M, m[i]);
    }
    float L = 0.f, w[NSPLIT];
#pragma unroll
    for (int i = 0; i < NSPLIT; i++) {
        w[i] = exp2f(m[i] - M);
        L += w[i] * lpart[i];
    }
    float inv = 1.0f / L;
    float c0 = 0.f, c1 = 0.f;
#pragma unroll
    for (int i = 0; i < NSPLIT; i++) {
        float2 ov = *(const float2*)&g_po[((size_t)i * MTOT + row) * HDIM + col];
        c0 += w[i] * ov.x;
        c1 += w[i] * ov.y;
    }
    *(uint32_t*)&g_ch[row * HDIM + col] = pack2h(c0 * inv, c1 * inv);
}

// ---------------------------------------------------------------------------
// Kernel 4: out = ctx[16384,64] @ Wo_sum[64,1024] + bo (fp16 MMA).
// BM=128, BN=64, K=64.  (Identical to the round-5/10/13 version.)
// ---------------------------------------------------------------------------
#define AP 72   // smem pitch (halves)
__global__ __launch_bounds__(256) void outproj_kernel(const float* __restrict__ bo,
                                                      float* __restrict__ out) {
    extern __shared__ __half smh[];
    __half* Ash = smh;              // ctx [128][AP]
    __half* Bsh = smh + 128 * AP;   // woT [64][AP]

    const int tid = threadIdx.x, warp = tid >> 5, lane = tid & 31;
    const int g = lane >> 2, tig = lane & 3;
    const int wm = warp & 3, wn = warp >> 2;
    const int row0 = blockIdx.x * 128, n0 = blockIdx.y * 64;

#pragma unroll
    for (int it = 0; it < 16; it++) {
        int id = tid + it * 256;                  // 0..4095 u32s
        int r = id >> 5, dp = (id & 31) * 2;
        *(uint32_t*)&Ash[r * AP + dp] = *(const uint32_t*)&g_ch[(row0 + r) * HDIM + dp];
    }
#pragma unroll
    for (int it = 0; it < 8; it++) {
        int id = tid + it * 256;                  // 0..2047 u32s
        int n = id >> 5, dp = (id & 31) * 2;
        *(uint32_t*)&Bsh[n * AP + dp] = *(const uint32_t*)&g_woh[(n0 + n) * HDIM + dp];
    }
    __syncthreads();

    float c[2][4][4];
#pragma unroll
    for (int mt = 0; mt < 2; mt++)
#pragma unroll
        for (int nt = 0; nt < 4; nt++)
#pragma unroll
            for (int j = 0; j < 4; j++) c[mt][nt][j] = 0.f;

#pragma unroll
    for (int kc = 0; kc < 4; kc++) {
        const int kb = kc * 16;
        uint32_t ah[2][4];
#pragma unroll
        for (int mt = 0; mt < 2; mt++) {
            int r = wm * 32 + mt * 16 + g;
            ah[mt][0] = *(const uint32_t*)&Ash[r * AP + kb + 2 * tig];
            ah[mt][1] = *(const uint32_t*)&Ash[(r + 8) * AP + kb + 2 * tig];
            ah[mt][2] = *(const uint32_t*)&Ash[r * AP + kb + 8 + 2 * tig];
            ah[mt][3] = *(const uint32_t*)&Ash[(r + 8) * AP + kb + 8 + 2 * tig];
        }
#pragma unroll
        for (int nt = 0; nt < 4; nt++) {
            int n = wn * 32 + nt * 8 + g;
            uint32_t bh0 = *(const uint32_t*)&Bsh[n * AP + kb + 2 * tig];
            uint32_t bh1 = *(const uint32_t*)&Bsh[n * AP + kb + 8 + 2 * tig];
#pragma unroll
            for (int mt = 0; mt < 2; mt++)
                mma_fp16(c[mt][nt], ah[mt][0], ah[mt][1], ah[mt][2], ah[mt][3], bh0, bh1);
        }
    }

#pragma unroll
    for (int mt = 0; mt < 2; mt++) {
#pragma unroll
        for (int nt = 0; nt < 4; nt++) {
            int r   = row0 + wm * 32 + mt * 16 + g;
            int col = n0 + wn * 32 + nt * 8 + 2 * tig;
            float bv0 = bo[col], bv1 = bo[col + 1];
            float2 v0 = make_float2(c[mt][nt][0] + bv0, c[mt][nt][1] + bv1);
            float2 v1 = make_float2(c[mt][nt][2] + bv0, c[mt][nt][3] + bv1);
            *(float2*)&out[r * DMODEL + col] = v0;
            *(float2*)&out[(r + 8) * DMODEL + col] = v1;
        }
    }
}

// ---------------------------------------------------------------------------
extern "C" void kernel_launch(void* const* d_in, const int* in_sizes, int n_in,
                              void* d_out, int out_size) {
    const float* query = (const float*)d_in[0];
    const float* key   = (const float*)d_in[1];
    const float* value = (const float*)d_in[2];
    const float* Wq    = (const float*)d_in[3];
    const float* bq    = (const float*)d_in[4];
    const float* Wk    = (const float*)d_in[5];
    const float* bk    = (const float*)d_in[6];
    const float* Wv    = (const float*)d_in[7];
    const float* bv    = (const float*)d_in[8];
    const float* Wo    = (const float*)d_in[9];
    const float* bo    = (const float*)d_in[10];
    float* out = (float*)d_out;

    const int ATTN_SMEM = (128 + 64 + 64) * 36 * (int)sizeof(uint32_t); // 36864
    const int OUTP_SMEM = (128 + 64) * AP * (int)sizeof(__half);        // 27648

    // proj needs 87 KB dynamic smem (idempotent attribute set, every launch)
    cudaFuncSetAttribute(proj_kernel,
                         cudaFuncAttributeMaxDynamicSharedMemorySize, PROJ_SMEM);

    wosum_kernel<<<256, 256>>>(Wo);
    proj_kernel<<<dim3(128, 3), 256, PROJ_SMEM>>>(query, key, value,
                                                  Wq, Wk, Wv, bq, bk, bv);
    attn_kernel<<<dim3(SS / 128, BB, NSPLIT), 256, ATTN_SMEM>>>();
    combine_kernel<<<MTOT / 8, 256>>>();
    outproj_kernel<<<dim3(MTOT / 128, DMODEL / 64), 256, OUTP_SMEM>>>(bo, out);
}